// round 2
// baseline (speedup 1.0000x reference)
#include <cuda_runtime.h>
#include <math.h>

// Shapes: B=2, T=16, C=30, H=W=64.  NIMG = B*T = 32 images, NPIX = 4096.
// Deform conv input is the reshape-scrambled view xr[j][c'] with
//   f1 = j*30+c', b = f1/480, c = (f1%480)/16, t = f1%16  ->  x[b][t][c].
// Output reshape is NOT scrambled: y1[j][o] -> (b=j/16, t=j%16, c=o).

#define NIMG 32
#define NPIX 4096
#define CPAD 32

// ---------------- scratch (device globals; no runtime allocation) -------------
__device__ __align__(16) float g_xr[NIMG * NPIX * CPAD];   // NHWC pad-32, 64 MB
__device__ float g_om[NIMG * 28 * NPIX];                   // offsets(18)+mask(9), ch-major
__device__ float g_y1[NIMG * 30 * NPIX];                   // deform+comp output
__device__ __align__(16) float g_Wc[9 * 30 * CPAD];        // combined comp@conv [tap][o][c]
__device__ __align__(16) float g_Wk1[9 * 27 * CPAD];       // offset/mask weights [tap][oc][c]
__device__ float g_sums[32];                               // BN sum / sumsq per channel
__device__ float g_stats[32];                              // mean / inv_std

// ---------------- K0: weight prep + zero stats --------------------------------
__global__ void k_prep(const float* __restrict__ comp_w, const float* __restrict__ conv_w,
                       const float* __restrict__ p_w, const float* __restrict__ m_w) {
    int t = blockIdx.x * blockDim.x + threadIdx.x;
    const int NWC = 9 * 30 * CPAD;          // 8640
    const int NW1 = 9 * 27 * CPAD;          // 7776
    if (t < NWC) {
        int n = t / (30 * CPAD);
        int r = t - n * (30 * CPAD);
        int o = r >> 5;
        int c = r & 31;
        float acc = 0.f;
        if (c < 30) {
            for (int m = 0; m < 90; m++)
                acc += comp_w[o * 90 + m] * conv_w[(m * 30 + c) * 9 + n];
        }
        g_Wc[t] = acc;
    } else if (t < NWC + NW1) {
        int u = t - NWC;
        int n = u / (27 * CPAD);
        int r = u - n * (27 * CPAD);
        int oc = r >> 5;
        int c = r & 31;
        float v = 0.f;
        if (c < 30)
            v = (oc < 18) ? p_w[(oc * 30 + c) * 9 + n] : m_w[((oc - 18) * 30 + c) * 9 + n];
        g_Wk1[u] = v;
    } else if (t < NWC + NW1 + 32) {
        g_sums[t - (NWC + NW1)] = 0.f;
    }
}

// ---------------- Kt: build NHWC pad-32 scrambled view -------------------------
__global__ void k_transpose(const float* __restrict__ x) {
    int t = blockIdx.x * blockDim.x + threadIdx.x;   // 131072 = NIMG*NPIX
    int j = t >> 12;
    int hw = t & 4095;
    float v[CPAD];
#pragma unroll
    for (int cp = 0; cp < 30; cp++) {
        int f1 = j * 30 + cp;
        int b = (f1 >= 480) ? 1 : 0;
        int rem = f1 - b * 480;
        int c = rem >> 4;
        int tt = rem & 15;
        v[cp] = x[((size_t)((b * 16 + tt) * 30 + c)) * NPIX + hw];
    }
    v[30] = 0.f; v[31] = 0.f;
    float4* dst = (float4*)(g_xr + (size_t)t * CPAD);
#pragma unroll
    for (int q = 0; q < 8; q++)
        dst[q] = make_float4(v[4 * q], v[4 * q + 1], v[4 * q + 2], v[4 * q + 3]);
}

// ---------------- K1: offset + mask 3x3 convs ----------------------------------
#define S1 18
__global__ void __launch_bounds__(256, 2) k_conv1(const float* __restrict__ p_b,
                                                  const float* __restrict__ m_b) {
    extern __shared__ float sm[];
    float* xt = sm;                       // [S1*S1*CPAD]
    float* wt = sm + S1 * S1 * CPAD;      // [9*27*CPAD]
    int blk = blockIdx.x;
    int j = blk >> 4;
    int tile = blk & 15;
    int th0 = (tile >> 2) << 4;
    int tw0 = (tile & 3) << 4;
    int tid = threadIdx.x;

    for (int pos = tid; pos < S1 * S1; pos += 256) {
        int rr = pos / S1, cc = pos % S1;
        int ih = th0 - 1 + rr, iw = tw0 - 1 + cc;
        float4* d = (float4*)(xt + pos * CPAD);
        if (ih >= 0 && ih < 64 && iw >= 0 && iw < 64) {
            const float4* s = (const float4*)(g_xr + (size_t)(j * NPIX + ih * 64 + iw) * CPAD);
#pragma unroll
            for (int q = 0; q < 8; q++) d[q] = s[q];
        } else {
#pragma unroll
            for (int q = 0; q < 8; q++) d[q] = make_float4(0.f, 0.f, 0.f, 0.f);
        }
    }
    for (int p = tid; p < 9 * 27 * CPAD / 4; p += 256)
        ((float4*)wt)[p] = ((const float4*)g_Wk1)[p];
    __syncthreads();

    int ty = tid >> 4, tx = tid & 15;
    int h = th0 + ty, w = tw0 + tx;
    float acc[27];
#pragma unroll
    for (int o = 0; o < 27; o++) acc[o] = 0.f;

    for (int n = 0; n < 9; n++) {
        int i = n / 3;
        int jj = n - i * 3;
        const float4* sp = (const float4*)(xt + ((ty + i) * S1 + (tx + jj)) * CPAD);
        float4 s4[8];
#pragma unroll
        for (int q = 0; q < 8; q++) s4[q] = sp[q];
#pragma unroll
        for (int o = 0; o < 27; o++) {
            const float4* wp = (const float4*)(wt + (n * 27 + o) * CPAD);
            float a0 = 0.f, a1 = 0.f, a2 = 0.f, a3 = 0.f;
#pragma unroll
            for (int q = 0; q < 8; q++) {
                float4 wv = wp[q];
                a0 += wv.x * s4[q].x; a1 += wv.y * s4[q].y;
                a2 += wv.z * s4[q].z; a3 += wv.w * s4[q].w;
            }
            acc[o] += (a0 + a1) + (a2 + a3);
        }
    }
    int hw = h * 64 + w;
    size_t ob = (size_t)j * 28 * NPIX + hw;
#pragma unroll
    for (int o = 0; o < 18; o++)
        g_om[ob + (size_t)o * NPIX] = acc[o] + p_b[o];
#pragma unroll
    for (int o = 18; o < 27; o++) {
        float z = acc[o] + m_b[o - 18];
        g_om[ob + (size_t)o * NPIX] = 1.f / (1.f + expf(-z));
    }
}

// ---------------- K2: fused deform sample + (comp@conv) matvec ------------------
#define HALO 4
#define TSZ 24
__device__ __forceinline__ void add_corner_g(float4* s4, const float* base, int qx, int qy, float g) {
    if (qx >= 1 && qx <= 64 && qy >= 1 && qy <= 64) {
        const float4* p = (const float4*)(base + (size_t)((qx - 1) * 64 + (qy - 1)) * CPAD);
#pragma unroll
        for (int q = 0; q < 8; q++) {
            float4 v = p[q];
            s4[q].x += g * v.x; s4[q].y += g * v.y;
            s4[q].z += g * v.z; s4[q].w += g * v.w;
        }
    }
}

__global__ void __launch_bounds__(256, 2) k_deform() {
    extern __shared__ float sm[];
    float* xt = sm;                        // [TSZ*TSZ*CPAD]
    float* wt = sm + TSZ * TSZ * CPAD;     // [9*30*CPAD]
    int blk = blockIdx.x;
    int j = blk >> 4;
    int tile = blk & 15;
    int th0 = (tile >> 2) << 4;
    int tw0 = (tile & 3) << 4;
    int tx0 = th0 - (HALO - 1);   // padded coord of smem row 0
    int ty0 = tw0 - (HALO - 1);
    int tid = threadIdx.x;

    for (int pos = tid; pos < TSZ * TSZ; pos += 256) {
        int rr = pos / TSZ, cc = pos % TSZ;
        int qx = tx0 + rr, qy = ty0 + cc;
        float4* d = (float4*)(xt + pos * CPAD);
        if (qx >= 1 && qx <= 64 && qy >= 1 && qy <= 64) {
            const float4* s = (const float4*)(g_xr + (size_t)(j * NPIX + (qx - 1) * 64 + (qy - 1)) * CPAD);
#pragma unroll
            for (int q = 0; q < 8; q++) d[q] = s[q];
        } else {
#pragma unroll
            for (int q = 0; q < 8; q++) d[q] = make_float4(0.f, 0.f, 0.f, 0.f);
        }
    }
    for (int p = tid; p < 9 * 30 * CPAD / 4; p += 256)
        ((float4*)wt)[p] = ((const float4*)g_Wc)[p];
    __syncthreads();

    int ty = tid >> 4, tx = tid & 15;
    int h = th0 + ty, w = tw0 + tx;
    int hw = h * 64 + w;
    const float* omb = g_om + (size_t)j * 28 * NPIX + hw;

    float acc[30];
#pragma unroll
    for (int o = 0; o < 30; o++) acc[o] = 0.f;

    for (int n = 0; n < 9; n++) {
        float offx = omb[(size_t)n * NPIX];
        float offy = omb[(size_t)(9 + n) * NPIX];
        float mk   = omb[(size_t)(18 + n) * NPIX];
        int dxi = n / 3;
        int dyi = n - dxi * 3;
        float p_x = (float)(h + dxi) + offx;   // = (h+1) + (dx-1) + off
        float p_y = (float)(w + dyi) + offy;
        float qfx = floorf(p_x), qfy = floorf(p_y);
        float ltx = fminf(fmaxf(qfx, 0.f), 65.f);
        float lty = fminf(fmaxf(qfy, 0.f), 65.f);
        float rbx = fminf(fmaxf(qfx + 1.f, 0.f), 65.f);
        float rby = fminf(fmaxf(qfy + 1.f, 0.f), 65.f);
        float pxc = fminf(fmaxf(p_x, 0.f), 65.f);
        float pyc = fminf(fmaxf(p_y, 0.f), 65.f);
        float gx_l = 1.f + ltx - pxc;
        float gx_r = 1.f - rbx + pxc;
        float gy_l = 1.f + lty - pyc;
        float gy_r = 1.f - rby + pyc;
        float glt = gx_l * gy_l * mk;
        float grb = gx_r * gy_r * mk;
        float glb = gx_l * gy_r * mk;
        float grt = gx_r * gy_l * mk;
        int ax = (int)ltx, ay = (int)lty, bx = (int)rbx, by = (int)rby;

        float4 s4[8];
        if (ax >= tx0 && bx < tx0 + TSZ && ay >= ty0 && by < ty0 + TSZ) {
            const float4* A  = (const float4*)(xt + ((ax - tx0) * TSZ + (ay - ty0)) * CPAD);
            const float4* Bp = (const float4*)(xt + ((bx - tx0) * TSZ + (by - ty0)) * CPAD);
            const float4* Cp = (const float4*)(xt + ((ax - tx0) * TSZ + (by - ty0)) * CPAD);
            const float4* Dp = (const float4*)(xt + ((bx - tx0) * TSZ + (ay - ty0)) * CPAD);
#pragma unroll
            for (int q = 0; q < 8; q++) {
                float4 a4 = A[q], b4 = Bp[q], c4 = Cp[q], d4 = Dp[q];
                s4[q].x = glt * a4.x + grb * b4.x + glb * c4.x + grt * d4.x;
                s4[q].y = glt * a4.y + grb * b4.y + glb * c4.y + grt * d4.y;
                s4[q].z = glt * a4.z + grb * b4.z + glb * c4.z + grt * d4.z;
                s4[q].w = glt * a4.w + grb * b4.w + glb * c4.w + grt * d4.w;
            }
        } else {
            // cold path: arbitrary offsets -> direct global gather
#pragma unroll
            for (int q = 0; q < 8; q++) s4[q] = make_float4(0.f, 0.f, 0.f, 0.f);
            const float* base = g_xr + (size_t)j * NPIX * CPAD;
            add_corner_g(s4, base, ax, ay, glt);
            add_corner_g(s4, base, bx, by, grb);
            add_corner_g(s4, base, ax, by, glb);
            add_corner_g(s4, base, bx, ay, grt);
        }

#pragma unroll
        for (int o = 0; o < 30; o++) {
            const float4* wp = (const float4*)(wt + (n * 30 + o) * CPAD);
            float a0 = 0.f, a1 = 0.f, a2 = 0.f, a3 = 0.f;
#pragma unroll
            for (int q = 0; q < 8; q++) {
                float4 wv = wp[q];
                a0 += wv.x * s4[q].x; a1 += wv.y * s4[q].y;
                a2 += wv.z * s4[q].z; a3 += wv.w * s4[q].w;
            }
            acc[o] += (a0 + a1) + (a2 + a3);
        }
    }

    float* yb = g_y1 + (size_t)j * 30 * NPIX + hw;
#pragma unroll
    for (int o = 0; o < 30; o++) yb[(size_t)o * NPIX] = acc[o];
}

// ---------------- K3: spec (temporal/depth) conv + BN partial sums --------------
__global__ void k_spec(const float* __restrict__ spec_w, float* __restrict__ out) {
    __shared__ float sw[16 * 48];
    __shared__ float bsum[32];
    int tid = threadIdx.x;
    for (int p = tid; p < 768; p += 256) sw[p] = spec_w[p];
    if (tid < 32) bsum[tid] = 0.f;
    __syncthreads();

    int idx = blockIdx.x * 256 + tid;        // < 245760 = 2*30*4096
    int b = idx / (30 * NPIX);
    int r = idx - b * (30 * NPIX);
    int d = r >> 12;
    int hw = r & 4095;

    float v[48];
#pragma unroll
    for (int ti = 0; ti < 16; ti++) {
#pragma unroll
        for (int kd = 0; kd < 3; kd++) {
            int dd = d + kd - 1;
            v[ti * 3 + kd] = (dd >= 0 && dd < 30)
                ? g_y1[((size_t)(b * 16 + ti) * 30 + dd) * NPIX + hw] : 0.f;
        }
    }
#pragma unroll
    for (int to = 0; to < 16; to++) {
        const float4* wp = (const float4*)(sw + to * 48);
        float a0 = 0.f, a1 = 0.f, a2 = 0.f, a3 = 0.f;
#pragma unroll
        for (int q = 0; q < 12; q++) {
            float4 wv = wp[q];
            a0 += wv.x * v[4 * q];     a1 += wv.y * v[4 * q + 1];
            a2 += wv.z * v[4 * q + 2]; a3 += wv.w * v[4 * q + 3];
        }
        float o = (a0 + a1) + (a2 + a3);
        out[((size_t)(b * 16 + to) * 30 + d) * NPIX + hw] = o;

        float s = o, q2 = o * o;
#pragma unroll
        for (int sh = 16; sh >= 1; sh >>= 1) {
            s  += __shfl_down_sync(0xffffffffu, s, sh);
            q2 += __shfl_down_sync(0xffffffffu, q2, sh);
        }
        if ((tid & 31) == 0) {
            atomicAdd(&bsum[to], s);
            atomicAdd(&bsum[16 + to], q2);
        }
    }
    __syncthreads();
    if (tid < 32) atomicAdd(&g_sums[tid], bsum[tid]);
}

// ---------------- K4: finalize BN stats ----------------------------------------
__global__ void k_stats() {
    int t = threadIdx.x;
    if (t < 16) {
        float n = 245760.f;
        float mean = g_sums[t] / n;
        float var = g_sums[16 + t] / n - mean * mean;
        g_stats[t] = mean;
        g_stats[16 + t] = rsqrtf(var + 1e-5f);
    }
}

// ---------------- K5: normalize + affine + relu (in place) ----------------------
__global__ void k_bn(float* __restrict__ out, const float* __restrict__ bn_g,
                     const float* __restrict__ bn_b) {
    int i4 = blockIdx.x * 256 + threadIdx.x;   // < 983040 float4s
    int ch = (i4 / 30720) & 15;
    float mean = g_stats[ch], inv = g_stats[16 + ch];
    float gg = bn_g[ch] * inv;
    float bb = bn_b[ch] - mean * gg;
    float4 v = ((float4*)out)[i4];
    v.x = fmaxf(v.x * gg + bb, 0.f);
    v.y = fmaxf(v.y * gg + bb, 0.f);
    v.z = fmaxf(v.z * gg + bb, 0.f);
    v.w = fmaxf(v.w * gg + bb, 0.f);
    ((float4*)out)[i4] = v;
}

// ---------------- launch --------------------------------------------------------
extern "C" void kernel_launch(void* const* d_in, const int* in_sizes, int n_in,
                              void* d_out, int out_size) {
    const float* x      = (const float*)d_in[0];
    const float* p_w    = (const float*)d_in[1];
    const float* p_b    = (const float*)d_in[2];
    const float* m_w    = (const float*)d_in[3];
    const float* m_b    = (const float*)d_in[4];
    const float* conv_w = (const float*)d_in[5];
    const float* comp_w = (const float*)d_in[6];
    const float* spec_w = (const float*)d_in[7];
    const float* bn_g   = (const float*)d_in[8];
    const float* bn_b   = (const float*)d_in[9];
    float* out = (float*)d_out;

    const int SM_K1 = S1 * S1 * CPAD * 4 + 9 * 27 * CPAD * 4;   // 72576
    const int SM_K2 = TSZ * TSZ * CPAD * 4 + 9 * 30 * CPAD * 4; // 108288
    cudaFuncSetAttribute(k_conv1, cudaFuncAttributeMaxDynamicSharedMemorySize, SM_K1);
    cudaFuncSetAttribute(k_deform, cudaFuncAttributeMaxDynamicSharedMemorySize, SM_K2);

    k_prep<<<65, 256>>>(comp_w, conv_w, p_w, m_w);
    k_transpose<<<512, 256>>>(x);
    k_conv1<<<512, 256, SM_K1>>>(p_b, m_b);
    k_deform<<<512, 256, SM_K2>>>();
    k_spec<<<960, 256>>>(spec_w, out);
    k_stats<<<1, 32>>>();
    k_bn<<<3840, 256>>>(out, bn_g, bn_b);
    (void)in_sizes; (void)n_in; (void)out_size;
}

// round 4
// speedup vs baseline: 1.5442x; 1.5442x over previous
#include <cuda_runtime.h>
#include <math.h>

// Shapes: B=2, T=16, C=30, H=W=64.  NIMG = B*T = 32 images, NPIX = 4096.
// Deform conv input is the reshape-scrambled view xr[j][c'] with
//   f1 = j*30+c', b = f1/480, c = (f1%480)/16, t = f1%16  ->  x[b][t][c].
// Output reshape is NOT scrambled: y1[j][o] -> (b=j/16, t=j%16, c=o).

#define NIMG 32
#define NPIX 4096
#define CPAD 32
#define XSTR 36   // smem per-pixel stride (floats). 36 = 9 float4s -> bank-group 9p mod 8
                  // covers all 8 groups; conflict degree 32 -> 4 (structural optimum).

// ---------------- scratch (device globals; no runtime allocation) -------------
__device__ __align__(16) float g_xr[NIMG * NPIX * CPAD];   // NHWC pad-32, 64 MB
__device__ float g_om[NIMG * 28 * NPIX];                   // offsets(18)+mask(9), ch-major
__device__ float g_y1[NIMG * 30 * NPIX];                   // deform+comp output
__device__ __align__(16) float g_Wc[9 * 30 * CPAD];        // combined comp@conv [tap][o][c]
__device__ __align__(16) float g_Wk1[9 * 27 * CPAD];       // offset/mask weights [tap][oc][c]
__device__ float g_sums[32];                               // BN sum / sumsq per channel
__device__ float g_stats[32];                              // mean / inv_std

// ---------------- K0: weight prep + zero stats --------------------------------
__global__ void k_prep(const float* __restrict__ comp_w, const float* __restrict__ conv_w,
                       const float* __restrict__ p_w, const float* __restrict__ m_w) {
    int t = blockIdx.x * blockDim.x + threadIdx.x;
    const int NWC = 9 * 30 * CPAD;          // 8640
    const int NW1 = 9 * 27 * CPAD;          // 7776
    if (t < NWC) {
        int n = t / (30 * CPAD);
        int r = t - n * (30 * CPAD);
        int o = r >> 5;
        int c = r & 31;
        float acc = 0.f;
        if (c < 30) {
            for (int m = 0; m < 90; m++)
                acc += comp_w[o * 90 + m] * conv_w[(m * 30 + c) * 9 + n];
        }
        g_Wc[t] = acc;
    } else if (t < NWC + NW1) {
        int u = t - NWC;
        int n = u / (27 * CPAD);
        int r = u - n * (27 * CPAD);
        int oc = r >> 5;
        int c = r & 31;
        float v = 0.f;
        if (c < 30)
            v = (oc < 18) ? p_w[(oc * 30 + c) * 9 + n] : m_w[((oc - 18) * 30 + c) * 9 + n];
        g_Wk1[u] = v;
    } else if (t < NWC + NW1 + 32) {
        g_sums[t - (NWC + NW1)] = 0.f;
    }
}

// ---------------- Kt: build NHWC pad-32 scrambled view -------------------------
__global__ void k_transpose(const float* __restrict__ x) {
    int t = blockIdx.x * blockDim.x + threadIdx.x;   // 131072 = NIMG*NPIX
    int j = t >> 12;
    int hw = t & 4095;
    float v[CPAD];
#pragma unroll
    for (int cp = 0; cp < 30; cp++) {
        int f1 = j * 30 + cp;
        int b = (f1 >= 480) ? 1 : 0;
        int rem = f1 - b * 480;
        int c = rem >> 4;
        int tt = rem & 15;
        v[cp] = x[((size_t)((b * 16 + tt) * 30 + c)) * NPIX + hw];
    }
    v[30] = 0.f; v[31] = 0.f;
    float4* dst = (float4*)(g_xr + (size_t)t * CPAD);
#pragma unroll
    for (int q = 0; q < 8; q++)
        dst[q] = make_float4(v[4 * q], v[4 * q + 1], v[4 * q + 2], v[4 * q + 3]);
}

// ---------------- K1: offset + mask 3x3 convs ----------------------------------
#define S1 18
__global__ void __launch_bounds__(256, 2) k_conv1(const float* __restrict__ p_b,
                                                  const float* __restrict__ m_b) {
    extern __shared__ float sm[];
    float* xt = sm;                       // [S1*S1*XSTR]
    float* wt = sm + S1 * S1 * XSTR;      // [9*27*CPAD]
    int blk = blockIdx.x;
    int j = blk >> 4;
    int tile = blk & 15;
    int th0 = (tile >> 2) << 4;
    int tw0 = (tile & 3) << 4;
    int tid = threadIdx.x;

    for (int pos = tid; pos < S1 * S1; pos += 256) {
        int rr = pos / S1, cc = pos % S1;
        int ih = th0 - 1 + rr, iw = tw0 - 1 + cc;
        float4* d = (float4*)(xt + pos * XSTR);
        if (ih >= 0 && ih < 64 && iw >= 0 && iw < 64) {
            const float4* s = (const float4*)(g_xr + (size_t)(j * NPIX + ih * 64 + iw) * CPAD);
#pragma unroll
            for (int q = 0; q < 8; q++) d[q] = s[q];
        } else {
#pragma unroll
            for (int q = 0; q < 8; q++) d[q] = make_float4(0.f, 0.f, 0.f, 0.f);
        }
    }
    for (int p = tid; p < 9 * 27 * CPAD / 4; p += 256)
        ((float4*)wt)[p] = ((const float4*)g_Wk1)[p];
    __syncthreads();

    int ty = tid >> 4, tx = tid & 15;
    int h = th0 + ty, w = tw0 + tx;
    float acc[27];
#pragma unroll
    for (int o = 0; o < 27; o++) acc[o] = 0.f;

    for (int n = 0; n < 9; n++) {
        int i = n / 3;
        int jj = n - i * 3;
        const float4* sp = (const float4*)(xt + ((ty + i) * S1 + (tx + jj)) * XSTR);
        float4 s4[8];
#pragma unroll
        for (int q = 0; q < 8; q++) s4[q] = sp[q];
#pragma unroll
        for (int o = 0; o < 27; o++) {
            const float4* wp = (const float4*)(wt + (n * 27 + o) * CPAD);
            float a0 = 0.f, a1 = 0.f, a2 = 0.f, a3 = 0.f;
#pragma unroll
            for (int q = 0; q < 8; q++) {
                float4 wv = wp[q];
                a0 += wv.x * s4[q].x; a1 += wv.y * s4[q].y;
                a2 += wv.z * s4[q].z; a3 += wv.w * s4[q].w;
            }
            acc[o] += (a0 + a1) + (a2 + a3);
        }
    }
    int hw = h * 64 + w;
    size_t ob = (size_t)j * 28 * NPIX + hw;
#pragma unroll
    for (int o = 0; o < 18; o++)
        g_om[ob + (size_t)o * NPIX] = acc[o] + p_b[o];
#pragma unroll
    for (int o = 18; o < 27; o++) {
        float z = acc[o] + m_b[o - 18];
        g_om[ob + (size_t)o * NPIX] = 1.f / (1.f + expf(-z));
    }
}

// ---------------- K2: fused deform sample + (comp@conv) matvec ------------------
// Tile rows cover padded coords [th0-1, th0+18] (20 rows): sufficient for any
// |offset| < 1 (offsets ~N(0,0.16)).  Larger offsets take the global slow path.
#define TSZ 20
__device__ __forceinline__ void add_corner_g(float4* s4, const float* base, int qx, int qy, float g) {
    if (qx >= 1 && qx <= 64 && qy >= 1 && qy <= 64) {
        const float4* p = (const float4*)(base + (size_t)((qx - 1) * 64 + (qy - 1)) * CPAD);
#pragma unroll
        for (int q = 0; q < 8; q++) {
            float4 v = p[q];
            s4[q].x += g * v.x; s4[q].y += g * v.y;
            s4[q].z += g * v.z; s4[q].w += g * v.w;
        }
    }
}

__global__ void __launch_bounds__(256, 2) k_deform() {
    extern __shared__ float sm[];
    float* xt = sm;                        // [TSZ*TSZ*XSTR]
    float* wt = sm + TSZ * TSZ * XSTR;     // [9*30*CPAD]
    int blk = blockIdx.x;
    int j = blk >> 4;
    int tile = blk & 15;
    int th0 = (tile >> 2) << 4;
    int tw0 = (tile & 3) << 4;
    int tx0 = th0 - 1;   // padded coord of smem row 0
    int ty0 = tw0 - 1;
    int tid = threadIdx.x;

    for (int pos = tid; pos < TSZ * TSZ; pos += 256) {
        int rr = pos / TSZ, cc = pos % TSZ;
        int qx = tx0 + rr, qy = ty0 + cc;
        float4* d = (float4*)(xt + pos * XSTR);
        if (qx >= 1 && qx <= 64 && qy >= 1 && qy <= 64) {
            const float4* s = (const float4*)(g_xr + (size_t)(j * NPIX + (qx - 1) * 64 + (qy - 1)) * CPAD);
#pragma unroll
            for (int q = 0; q < 8; q++) d[q] = s[q];
        } else {
#pragma unroll
            for (int q = 0; q < 8; q++) d[q] = make_float4(0.f, 0.f, 0.f, 0.f);
        }
    }
    for (int p = tid; p < 9 * 30 * CPAD / 4; p += 256)
        ((float4*)wt)[p] = ((const float4*)g_Wc)[p];
    __syncthreads();

    int ty = tid >> 4, tx = tid & 15;
    int h = th0 + ty, w = tw0 + tx;
    int hw = h * 64 + w;
    const float* omb = g_om + (size_t)j * 28 * NPIX + hw;

    float acc[30];
#pragma unroll
    for (int o = 0; o < 30; o++) acc[o] = 0.f;

    for (int n = 0; n < 9; n++) {
        float offx = omb[(size_t)n * NPIX];
        float offy = omb[(size_t)(9 + n) * NPIX];
        float mk   = omb[(size_t)(18 + n) * NPIX];
        int dxi = n / 3;
        int dyi = n - dxi * 3;
        float p_x = (float)(h + dxi) + offx;   // = (h+1) + (dx-1) + off
        float p_y = (float)(w + dyi) + offy;
        float qfx = floorf(p_x), qfy = floorf(p_y);
        float ltx = fminf(fmaxf(qfx, 0.f), 65.f);
        float lty = fminf(fmaxf(qfy, 0.f), 65.f);
        float rbx = fminf(fmaxf(qfx + 1.f, 0.f), 65.f);
        float rby = fminf(fmaxf(qfy + 1.f, 0.f), 65.f);
        float pxc = fminf(fmaxf(p_x, 0.f), 65.f);
        float pyc = fminf(fmaxf(p_y, 0.f), 65.f);
        float gx_l = 1.f + ltx - pxc;
        float gx_r = 1.f - rbx + pxc;
        float gy_l = 1.f + lty - pyc;
        float gy_r = 1.f - rby + pyc;
        float glt = gx_l * gy_l * mk;
        float grb = gx_r * gy_r * mk;
        float glb = gx_l * gy_r * mk;
        float grt = gx_r * gy_l * mk;
        int ax = (int)ltx, ay = (int)lty, bx = (int)rbx, by = (int)rby;

        float4 s4[8];
        if (ax >= tx0 && bx < tx0 + TSZ && ay >= ty0 && by < ty0 + TSZ) {
            const float4* A  = (const float4*)(xt + ((ax - tx0) * TSZ + (ay - ty0)) * XSTR);
            const float4* Bp = (const float4*)(xt + ((bx - tx0) * TSZ + (by - ty0)) * XSTR);
            const float4* Cp = (const float4*)(xt + ((ax - tx0) * TSZ + (by - ty0)) * XSTR);
            const float4* Dp = (const float4*)(xt + ((bx - tx0) * TSZ + (ay - ty0)) * XSTR);
#pragma unroll
            for (int q = 0; q < 8; q++) {
                float4 a4 = A[q], b4 = Bp[q], c4 = Cp[q], d4 = Dp[q];
                s4[q].x = glt * a4.x + grb * b4.x + glb * c4.x + grt * d4.x;
                s4[q].y = glt * a4.y + grb * b4.y + glb * c4.y + grt * d4.y;
                s4[q].z = glt * a4.z + grb * b4.z + glb * c4.z + grt * d4.z;
                s4[q].w = glt * a4.w + grb * b4.w + glb * c4.w + grt * d4.w;
            }
        } else {
            // cold path: arbitrary offsets -> direct global gather
#pragma unroll
            for (int q = 0; q < 8; q++) s4[q] = make_float4(0.f, 0.f, 0.f, 0.f);
            const float* base = g_xr + (size_t)j * NPIX * CPAD;
            add_corner_g(s4, base, ax, ay, glt);
            add_corner_g(s4, base, bx, by, grb);
            add_corner_g(s4, base, ax, by, glb);
            add_corner_g(s4, base, bx, ay, grt);
        }

#pragma unroll
        for (int o = 0; o < 30; o++) {
            const float4* wp = (const float4*)(wt + (n * 30 + o) * CPAD);
            float a0 = 0.f, a1 = 0.f, a2 = 0.f, a3 = 0.f;
#pragma unroll
            for (int q = 0; q < 8; q++) {
                float4 wv = wp[q];
                a0 += wv.x * s4[q].x; a1 += wv.y * s4[q].y;
                a2 += wv.z * s4[q].z; a3 += wv.w * s4[q].w;
            }
            acc[o] += (a0 + a1) + (a2 + a3);
        }
    }

    float* yb = g_y1 + (size_t)j * 30 * NPIX + hw;
#pragma unroll
    for (int o = 0; o < 30; o++) yb[(size_t)o * NPIX] = acc[o];
}

// ---------------- K3: spec (temporal/depth) conv + BN partial sums --------------
__global__ void k_spec(const float* __restrict__ spec_w, float* __restrict__ out) {
    __shared__ float sw[16 * 48];
    __shared__ float bsum[32];
    int tid = threadIdx.x;
    for (int p = tid; p < 768; p += 256) sw[p] = spec_w[p];
    if (tid < 32) bsum[tid] = 0.f;
    __syncthreads();

    int idx = blockIdx.x * 256 + tid;        // < 245760 = 2*30*4096
    int b = idx / (30 * NPIX);
    int r = idx - b * (30 * NPIX);
    int d = r >> 12;
    int hw = r & 4095;

    float v[48];
#pragma unroll
    for (int ti = 0; ti < 16; ti++) {
#pragma unroll
        for (int kd = 0; kd < 3; kd++) {
            int dd = d + kd - 1;
            v[ti * 3 + kd] = (dd >= 0 && dd < 30)
                ? g_y1[((size_t)(b * 16 + ti) * 30 + dd) * NPIX + hw] : 0.f;
        }
    }
#pragma unroll
    for (int to = 0; to < 16; to++) {
        const float4* wp = (const float4*)(sw + to * 48);
        float a0 = 0.f, a1 = 0.f, a2 = 0.f, a3 = 0.f;
#pragma unroll
        for (int q = 0; q < 12; q++) {
            float4 wv = wp[q];
            a0 += wv.x * v[4 * q];     a1 += wv.y * v[4 * q + 1];
            a2 += wv.z * v[4 * q + 2]; a3 += wv.w * v[4 * q + 3];
        }
        float o = (a0 + a1) + (a2 + a3);
        out[((size_t)(b * 16 + to) * 30 + d) * NPIX + hw] = o;

        float s = o, q2 = o * o;
#pragma unroll
        for (int sh = 16; sh >= 1; sh >>= 1) {
            s  += __shfl_down_sync(0xffffffffu, s, sh);
            q2 += __shfl_down_sync(0xffffffffu, q2, sh);
        }
        if ((tid & 31) == 0) {
            atomicAdd(&bsum[to], s);
            atomicAdd(&bsum[16 + to], q2);
        }
    }
    __syncthreads();
    if (tid < 32) atomicAdd(&g_sums[tid], bsum[tid]);
}

// ---------------- K4: finalize BN stats ----------------------------------------
__global__ void k_stats() {
    int t = threadIdx.x;
    if (t < 16) {
        float n = 245760.f;
        float mean = g_sums[t] / n;
        float var = g_sums[16 + t] / n - mean * mean;
        g_stats[t] = mean;
        g_stats[16 + t] = rsqrtf(var + 1e-5f);
    }
}

// ---------------- K5: normalize + affine + relu (in place) ----------------------
__global__ void k_bn(float* __restrict__ out, const float* __restrict__ bn_g,
                     const float* __restrict__ bn_b) {
    int i4 = blockIdx.x * 256 + threadIdx.x;   // < 983040 float4s
    int ch = (i4 / 30720) & 15;
    float mean = g_stats[ch], inv = g_stats[16 + ch];
    float gg = bn_g[ch] * inv;
    float bb = bn_b[ch] - mean * gg;
    float4 v = ((float4*)out)[i4];
    v.x = fmaxf(v.x * gg + bb, 0.f);
    v.y = fmaxf(v.y * gg + bb, 0.f);
    v.z = fmaxf(v.z * gg + bb, 0.f);
    v.w = fmaxf(v.w * gg + bb, 0.f);
    ((float4*)out)[i4] = v;
}

// ---------------- launch --------------------------------------------------------
extern "C" void kernel_launch(void* const* d_in, const int* in_sizes, int n_in,
                              void* d_out, int out_size) {
    const float* x      = (const float*)d_in[0];
    const float* p_w    = (const float*)d_in[1];
    const float* p_b    = (const float*)d_in[2];
    const float* m_w    = (const float*)d_in[3];
    const float* m_b    = (const float*)d_in[4];
    const float* conv_w = (const float*)d_in[5];
    const float* comp_w = (const float*)d_in[6];
    const float* spec_w = (const float*)d_in[7];
    const float* bn_g   = (const float*)d_in[8];
    const float* bn_b   = (const float*)d_in[9];
    float* out = (float*)d_out;

    const int SM_K1 = S1 * S1 * XSTR * 4 + 9 * 27 * CPAD * 4;   // 77760
    const int SM_K2 = TSZ * TSZ * XSTR * 4 + 9 * 30 * CPAD * 4; // 92160
    cudaFuncSetAttribute(k_conv1, cudaFuncAttributeMaxDynamicSharedMemorySize, SM_K1);
    cudaFuncSetAttribute(k_deform, cudaFuncAttributeMaxDynamicSharedMemorySize, SM_K2);

    k_prep<<<65, 256>>>(comp_w, conv_w, p_w, m_w);
    k_transpose<<<512, 256>>>(x);
    k_conv1<<<512, 256, SM_K1>>>(p_b, m_b);
    k_deform<<<512, 256, SM_K2>>>();
    k_spec<<<960, 256>>>(spec_w, out);
    k_stats<<<1, 32>>>();
    k_bn<<<3840, 256>>>(out, bn_g, bn_b);
    (void)in_sizes; (void)n_in; (void)out_size;
}

// round 6
// speedup vs baseline: 1.8815x; 1.2185x over previous
#include <cuda_runtime.h>
#include <math.h>

// Shapes: B=2, T=16, C=30, H=W=64.  NIMG = B*T = 32 images, NPIX = 4096.
// Deform conv input is the reshape-scrambled view xr[j][c'] with
//   f1 = j*30+c', b = f1/480, c = (f1%480)/16, t = f1%16  ->  x[b][t][c].
// Output reshape is NOT scrambled: y1[j][o] -> (b=j/16, t=j%16, c=o).

#define NIMG 32
#define NPIX 4096
#define CPAD 32
#define XSTR 36   // smem per-pixel stride (floats): 9 float4s -> all 8 bank groups hit.

// ---------------- scratch (device globals; no runtime allocation) -------------
__device__ __align__(16) float g_xr[NIMG * NPIX * CPAD];   // NHWC pad-32, 64 MB
__device__ float g_om[NIMG * 28 * NPIX];                   // offsets(18)+mask(9), ch-major
__device__ float g_y1[NIMG * 30 * NPIX];                   // deform+comp output
__device__ __align__(16) float g_Wc[9 * 30 * CPAD];        // combined comp@conv [tap][o][c]
__device__ __align__(16) float g_Wk1[9 * 27 * CPAD];       // offset/mask weights [tap][oc][c]
__device__ float g_sums[32];                               // BN sum / sumsq per channel
__device__ float g_stats[32];                              // mean / inv_std

// ---------------- K0: weight prep + zero stats --------------------------------
__global__ void k_prep(const float* __restrict__ comp_w, const float* __restrict__ conv_w,
                       const float* __restrict__ p_w, const float* __restrict__ m_w) {
    int t = blockIdx.x * blockDim.x + threadIdx.x;
    const int NWC = 9 * 30 * CPAD;          // 8640
    const int NW1 = 9 * 27 * CPAD;          // 7776
    if (t < NWC) {
        int n = t / (30 * CPAD);
        int r = t - n * (30 * CPAD);
        int o = r >> 5;
        int c = r & 31;
        float acc = 0.f;
        if (c < 30) {
            for (int m = 0; m < 90; m++)
                acc += comp_w[o * 90 + m] * conv_w[(m * 30 + c) * 9 + n];
        }
        g_Wc[t] = acc;
    } else if (t < NWC + NW1) {
        int u = t - NWC;
        int n = u / (27 * CPAD);
        int r = u - n * (27 * CPAD);
        int oc = r >> 5;
        int c = r & 31;
        float v = 0.f;
        if (c < 30)
            v = (oc < 18) ? p_w[(oc * 30 + c) * 9 + n] : m_w[((oc - 18) * 30 + c) * 9 + n];
        g_Wk1[u] = v;
    } else if (t < NWC + NW1 + 32) {
        g_sums[t - (NWC + NW1)] = 0.f;
    }
}

// ---------------- Kt: build NHWC pad-32 scrambled view -------------------------
__global__ void k_transpose(const float* __restrict__ x) {
    int t = blockIdx.x * blockDim.x + threadIdx.x;   // 131072 = NIMG*NPIX
    int j = t >> 12;
    int hw = t & 4095;
    float v[CPAD];
#pragma unroll
    for (int cp = 0; cp < 30; cp++) {
        int f1 = j * 30 + cp;
        int b = (f1 >= 480) ? 1 : 0;
        int rem = f1 - b * 480;
        int c = rem >> 4;
        int tt = rem & 15;
        v[cp] = x[((size_t)((b * 16 + tt) * 30 + c)) * NPIX + hw];
    }
    v[30] = 0.f; v[31] = 0.f;
    float4* dst = (float4*)(g_xr + (size_t)t * CPAD);
#pragma unroll
    for (int q = 0; q < 8; q++)
        dst[q] = make_float4(v[4 * q], v[4 * q + 1], v[4 * q + 2], v[4 * q + 3]);
}

// ---------------- K1: offset + mask 3x3 convs (P=2 pixels/thread) --------------
#define CTS 34
__global__ void __launch_bounds__(512, 1) k_conv1(const float* __restrict__ p_b,
                                                  const float* __restrict__ m_b) {
    extern __shared__ float sm[];
    float* xt = sm;                        // [CTS*CTS*XSTR]
    float* wt = sm + CTS * CTS * XSTR;     // [9*27*32]
    int blk = blockIdx.x;
    int j = blk >> 2;
    int tile = blk & 3;
    int th0 = (tile >> 1) << 5;
    int tw0 = (tile & 1) << 5;
    int tid = threadIdx.x;

    for (int pos = tid; pos < CTS * CTS; pos += 512) {
        int rr = pos / CTS, cc = pos % CTS;
        int ih = th0 - 1 + rr, iw = tw0 - 1 + cc;
        float4* d = (float4*)(xt + pos * XSTR);
        if (ih >= 0 && ih < 64 && iw >= 0 && iw < 64) {
            const float4* s = (const float4*)(g_xr + (size_t)(j * NPIX + ih * 64 + iw) * CPAD);
#pragma unroll
            for (int q = 0; q < 8; q++) d[q] = s[q];
        } else {
#pragma unroll
            for (int q = 0; q < 8; q++) d[q] = make_float4(0.f, 0.f, 0.f, 0.f);
        }
    }
    for (int p = tid; p < 9 * 27 * 32 / 4; p += 512)
        ((float4*)wt)[p] = ((const float4*)g_Wk1)[p];
    __syncthreads();

    int tx = tid & 31, ty = tid >> 5;      // ty 0..15
    int h0 = th0 + ty;
    int w = tw0 + tx;
    float acc0[27], acc1[27];
#pragma unroll
    for (int o = 0; o < 27; o++) { acc0[o] = 0.f; acc1[o] = 0.f; }

    for (int n = 0; n < 9; n++) {
        int i = n / 3;
        int jj = n - i * 3;
        const float* b0 = xt + ((ty + i) * CTS + (tx + jj)) * XSTR;
        const float* b1 = b0 + 16 * CTS * XSTR;
#pragma unroll
        for (int half = 0; half < 2; half++) {
            int co = half << 4;
            float4 sA[4], sB[4];
            const float4* p0 = (const float4*)(b0 + co);
            const float4* p1 = (const float4*)(b1 + co);
#pragma unroll
            for (int q = 0; q < 4; q++) { sA[q] = p0[q]; sB[q] = p1[q]; }
            const float* wb = wt + (n * 27) * 32 + co;
#pragma unroll
            for (int o = 0; o < 27; o++) {
                const float4* wp = (const float4*)(wb + o * 32);
                float4 w0 = wp[0], w1 = wp[1], w2 = wp[2], w3 = wp[3];
                float u0 = w0.x * sA[0].x + w0.y * sA[0].y + w0.z * sA[0].z + w0.w * sA[0].w
                         + w1.x * sA[1].x + w1.y * sA[1].y + w1.z * sA[1].z + w1.w * sA[1].w
                         + w2.x * sA[2].x + w2.y * sA[2].y + w2.z * sA[2].z + w2.w * sA[2].w
                         + w3.x * sA[3].x + w3.y * sA[3].y + w3.z * sA[3].z + w3.w * sA[3].w;
                float u1 = w0.x * sB[0].x + w0.y * sB[0].y + w0.z * sB[0].z + w0.w * sB[0].w
                         + w1.x * sB[1].x + w1.y * sB[1].y + w1.z * sB[1].z + w1.w * sB[1].w
                         + w2.x * sB[2].x + w2.y * sB[2].y + w2.z * sB[2].z + w2.w * sB[2].w
                         + w3.x * sB[3].x + w3.y * sB[3].y + w3.z * sB[3].z + w3.w * sB[3].w;
                acc0[o] += u0;
                acc1[o] += u1;
            }
        }
    }
    int hw0 = h0 * 64 + w;
    size_t ob0 = (size_t)j * 28 * NPIX + hw0;
    size_t ob1 = ob0 + 16 * 64;
#pragma unroll
    for (int o = 0; o < 18; o++) {
        g_om[ob0 + (size_t)o * NPIX] = acc0[o] + p_b[o];
        g_om[ob1 + (size_t)o * NPIX] = acc1[o] + p_b[o];
    }
#pragma unroll
    for (int o = 18; o < 27; o++) {
        float z0 = acc0[o] + m_b[o - 18];
        float z1 = acc1[o] + m_b[o - 18];
        g_om[ob0 + (size_t)o * NPIX] = 1.f / (1.f + expf(-z0));
        g_om[ob1 + (size_t)o * NPIX] = 1.f / (1.f + expf(-z1));
    }
}

// ---------------- K2: fused deform sample + matvec (P=2 pixels/thread) ----------
// smem covers padded rows/cols [th0-1, th0+34]: enough for |offset| < 1 at all taps
// (dxi up to 2).  Larger offsets fall back to a guarded global gather.
#define DTS 36
__device__ __forceinline__ void add_corner_g(float4* s, const float* base,
                                             int qx, int qy, float g, int co) {
    if (qx >= 1 && qx <= 64 && qy >= 1 && qy <= 64) {
        const float4* p = (const float4*)(base + (size_t)((qx - 1) * 64 + (qy - 1)) * CPAD + co);
#pragma unroll
        for (int q = 0; q < 4; q++) {
            float4 v = p[q];
            s[q].x += g * v.x; s[q].y += g * v.y;
            s[q].z += g * v.z; s[q].w += g * v.w;
        }
    }
}

__global__ void __launch_bounds__(512, 1) k_deform() {
    extern __shared__ float sm[];
    float* xt = sm;                        // [DTS*DTS*XSTR]
    float* wt = sm + DTS * DTS * XSTR;     // [9*30*32]
    int blk = blockIdx.x;
    int j = blk >> 2;
    int tile = blk & 3;
    int th0 = (tile >> 1) << 5;
    int tw0 = (tile & 1) << 5;
    int tx0 = th0 - 1;   // padded coord of smem row 0
    int ty0 = tw0 - 1;
    int tid = threadIdx.x;

    for (int pos = tid; pos < DTS * DTS; pos += 512) {
        int rr = pos / DTS, cc = pos % DTS;
        int qx = tx0 + rr, qy = ty0 + cc;
        float4* d = (float4*)(xt + pos * XSTR);
        if (qx >= 1 && qx <= 64 && qy >= 1 && qy <= 64) {
            const float4* s = (const float4*)(g_xr + (size_t)(j * NPIX + (qx - 1) * 64 + (qy - 1)) * CPAD);
#pragma unroll
            for (int q = 0; q < 8; q++) d[q] = s[q];
        } else {
#pragma unroll
            for (int q = 0; q < 8; q++) d[q] = make_float4(0.f, 0.f, 0.f, 0.f);
        }
    }
    for (int p = tid; p < 9 * 30 * 32 / 4; p += 512)
        ((float4*)wt)[p] = ((const float4*)g_Wc)[p];
    __syncthreads();

    int tx = tid & 31, ty = tid >> 5;      // ty 0..15
    int h0 = th0 + ty, h1 = h0 + 16;
    int w = tw0 + tx;
    const float* om0 = g_om + (size_t)j * 28 * NPIX + h0 * 64 + w;
    const float* om1 = om0 + 16 * 64;
    const float* gb = g_xr + (size_t)j * NPIX * CPAD;

    float acc0[30], acc1[30];
#pragma unroll
    for (int o = 0; o < 30; o++) { acc0[o] = 0.f; acc1[o] = 0.f; }

    for (int n = 0; n < 9; n++) {
        int dxi = n / 3;
        int dyi = n - dxi * 3;

        // ---- pixel 0 geometry ----
        float ox0 = om0[(size_t)n * NPIX];
        float oy0 = om0[(size_t)(9 + n) * NPIX];
        float mk0 = om0[(size_t)(18 + n) * NPIX];
        float px0 = (float)(h0 + dxi) + ox0;
        float py0 = (float)(w + dyi) + oy0;
        float qfx0 = floorf(px0), qfy0 = floorf(py0);
        float lx0 = fminf(fmaxf(qfx0, 0.f), 65.f);
        float ly0 = fminf(fmaxf(qfy0, 0.f), 65.f);
        float rx0 = fminf(fmaxf(qfx0 + 1.f, 0.f), 65.f);
        float ry0 = fminf(fmaxf(qfy0 + 1.f, 0.f), 65.f);
        float pxc0 = fminf(fmaxf(px0, 0.f), 65.f);
        float pyc0 = fminf(fmaxf(py0, 0.f), 65.f);
        float gxl0 = 1.f + lx0 - pxc0, gxr0 = 1.f - rx0 + pxc0;
        float gyl0 = 1.f + ly0 - pyc0, gyr0 = 1.f - ry0 + pyc0;
        float g0lt = gxl0 * gyl0 * mk0, g0rb = gxr0 * gyr0 * mk0;
        float g0lb = gxl0 * gyr0 * mk0, g0rt = gxr0 * gyl0 * mk0;
        int a0x = (int)lx0, a0y = (int)ly0, b0x = (int)rx0, b0y = (int)ry0;
        bool f0 = (a0x >= tx0) & (b0x < tx0 + DTS) & (a0y >= ty0) & (b0y < ty0 + DTS);

        // ---- pixel 1 geometry ----
        float ox1 = om1[(size_t)n * NPIX];
        float oy1 = om1[(size_t)(9 + n) * NPIX];
        float mk1 = om1[(size_t)(18 + n) * NPIX];
        float px1 = (float)(h1 + dxi) + ox1;
        float py1 = (float)(w + dyi) + oy1;
        float qfx1 = floorf(px1), qfy1 = floorf(py1);
        float lx1 = fminf(fmaxf(qfx1, 0.f), 65.f);
        float ly1 = fminf(fmaxf(qfy1, 0.f), 65.f);
        float rx1 = fminf(fmaxf(qfx1 + 1.f, 0.f), 65.f);
        float ry1 = fminf(fmaxf(qfy1 + 1.f, 0.f), 65.f);
        float pxc1 = fminf(fmaxf(px1, 0.f), 65.f);
        float pyc1 = fminf(fmaxf(py1, 0.f), 65.f);
        float gxl1 = 1.f + lx1 - pxc1, gxr1 = 1.f - rx1 + pxc1;
        float gyl1 = 1.f + ly1 - pyc1, gyr1 = 1.f - ry1 + pyc1;
        float g1lt = gxl1 * gyl1 * mk1, g1rb = gxr1 * gyr1 * mk1;
        float g1lb = gxl1 * gyr1 * mk1, g1rt = gxr1 * gyl1 * mk1;
        int a1x = (int)lx1, a1y = (int)ly1, b1x = (int)rx1, b1y = (int)ry1;
        bool f1 = (a1x >= tx0) & (b1x < tx0 + DTS) & (a1y >= ty0) & (b1y < ty0 + DTS);

#pragma unroll
        for (int half = 0; half < 2; half++) {
            int co = half << 4;
            float4 sA[4], sB[4];

            if (f0) {
                const float4* A = (const float4*)(xt + ((a0x - tx0) * DTS + (a0y - ty0)) * XSTR + co);
                const float4* B = (const float4*)(xt + ((b0x - tx0) * DTS + (b0y - ty0)) * XSTR + co);
                const float4* C = (const float4*)(xt + ((a0x - tx0) * DTS + (b0y - ty0)) * XSTR + co);
                const float4* D = (const float4*)(xt + ((b0x - tx0) * DTS + (a0y - ty0)) * XSTR + co);
#pragma unroll
                for (int q = 0; q < 4; q++) {
                    float4 a = A[q], b = B[q], c = C[q], d = D[q];
                    sA[q].x = g0lt * a.x + g0rb * b.x + g0lb * c.x + g0rt * d.x;
                    sA[q].y = g0lt * a.y + g0rb * b.y + g0lb * c.y + g0rt * d.y;
                    sA[q].z = g0lt * a.z + g0rb * b.z + g0lb * c.z + g0rt * d.z;
                    sA[q].w = g0lt * a.w + g0rb * b.w + g0lb * c.w + g0rt * d.w;
                }
            } else {
#pragma unroll
                for (int q = 0; q < 4; q++) sA[q] = make_float4(0.f, 0.f, 0.f, 0.f);
                add_corner_g(sA, gb, a0x, a0y, g0lt, co);
                add_corner_g(sA, gb, b0x, b0y, g0rb, co);
                add_corner_g(sA, gb, a0x, b0y, g0lb, co);
                add_corner_g(sA, gb, b0x, a0y, g0rt, co);
            }

            if (f1) {
                const float4* A = (const float4*)(xt + ((a1x - tx0) * DTS + (a1y - ty0)) * XSTR + co);
                const float4* B = (const float4*)(xt + ((b1x - tx0) * DTS + (b1y - ty0)) * XSTR + co);
                const float4* C = (const float4*)(xt + ((a1x - tx0) * DTS + (b1y - ty0)) * XSTR + co);
                const float4* D = (const float4*)(xt + ((b1x - tx0) * DTS + (a1y - ty0)) * XSTR + co);
#pragma unroll
                for (int q = 0; q < 4; q++) {
                    float4 a = A[q], b = B[q], c = C[q], d = D[q];
                    sB[q].x = g1lt * a.x + g1rb * b.x + g1lb * c.x + g1rt * d.x;
                    sB[q].y = g1lt * a.y + g1rb * b.y + g1lb * c.y + g1rt * d.y;
                    sB[q].z = g1lt * a.z + g1rb * b.z + g1lb * c.z + g1rt * d.z;
                    sB[q].w = g1lt * a.w + g1rb * b.w + g1lb * c.w + g1rt * d.w;
                }
            } else {
#pragma unroll
                for (int q = 0; q < 4; q++) sB[q] = make_float4(0.f, 0.f, 0.f, 0.f);
                add_corner_g(sB, gb, a1x, a1y, g1lt, co);
                add_corner_g(sB, gb, b1x, b1y, g1rb, co);
                add_corner_g(sB, gb, a1x, b1y, g1lb, co);
                add_corner_g(sB, gb, b1x, a1y, g1rt, co);
            }

            const float* wb = wt + (n * 30) * 32 + co;
#pragma unroll
            for (int o = 0; o < 30; o++) {
                const float4* wp = (const float4*)(wb + o * 32);
                float4 w0 = wp[0], w1 = wp[1], w2 = wp[2], w3 = wp[3];
                float u0 = w0.x * sA[0].x + w0.y * sA[0].y + w0.z * sA[0].z + w0.w * sA[0].w
                         + w1.x * sA[1].x + w1.y * sA[1].y + w1.z * sA[1].z + w1.w * sA[1].w
                         + w2.x * sA[2].x + w2.y * sA[2].y + w2.z * sA[2].z + w2.w * sA[2].w
                         + w3.x * sA[3].x + w3.y * sA[3].y + w3.z * sA[3].z + w3.w * sA[3].w;
                float u1 = w0.x * sB[0].x + w0.y * sB[0].y + w0.z * sB[0].z + w0.w * sB[0].w
                         + w1.x * sB[1].x + w1.y * sB[1].y + w1.z * sB[1].z + w1.w * sB[1].w
                         + w2.x * sB[2].x + w2.y * sB[2].y + w2.z * sB[2].z + w2.w * sB[2].w
                         + w3.x * sB[3].x + w3.y * sB[3].y + w3.z * sB[3].z + w3.w * sB[3].w;
                acc0[o] += u0;
                acc1[o] += u1;
            }
        }
    }

    int hw0 = h0 * 64 + w;
    float* yb0 = g_y1 + (size_t)j * 30 * NPIX + hw0;
    float* yb1 = yb0 + 16 * 64;
#pragma unroll
    for (int o = 0; o < 30; o++) {
        yb0[(size_t)o * NPIX] = acc0[o];
        yb1[(size_t)o * NPIX] = acc1[o];
    }
}

// ---------------- K3: spec (temporal/depth) conv + BN partial sums --------------
__global__ void k_spec(const float* __restrict__ spec_w, float* __restrict__ out) {
    __shared__ float sw[16 * 48];
    __shared__ float bsum[32];
    int tid = threadIdx.x;
    for (int p = tid; p < 768; p += 256) sw[p] = spec_w[p];
    if (tid < 32) bsum[tid] = 0.f;
    __syncthreads();

    int idx = blockIdx.x * 256 + tid;        // < 245760 = 2*30*4096
    int b = idx / (30 * NPIX);
    int r = idx - b * (30 * NPIX);
    int d = r >> 12;
    int hw = r & 4095;

    float v[48];
#pragma unroll
    for (int ti = 0; ti < 16; ti++) {
#pragma unroll
        for (int kd = 0; kd < 3; kd++) {
            int dd = d + kd - 1;
            v[ti * 3 + kd] = (dd >= 0 && dd < 30)
                ? g_y1[((size_t)(b * 16 + ti) * 30 + dd) * NPIX + hw] : 0.f;
        }
    }
#pragma unroll
    for (int to = 0; to < 16; to++) {
        const float4* wp = (const float4*)(sw + to * 48);
        float a0 = 0.f, a1 = 0.f, a2 = 0.f, a3 = 0.f;
#pragma unroll
        for (int q = 0; q < 12; q++) {
            float4 wv = wp[q];
            a0 += wv.x * v[4 * q];     a1 += wv.y * v[4 * q + 1];
            a2 += wv.z * v[4 * q + 2]; a3 += wv.w * v[4 * q + 3];
        }
        float o = (a0 + a1) + (a2 + a3);
        out[((size_t)(b * 16 + to) * 30 + d) * NPIX + hw] = o;

        float s = o, q2 = o * o;
#pragma unroll
        for (int sh = 16; sh >= 1; sh >>= 1) {
            s  += __shfl_down_sync(0xffffffffu, s, sh);
            q2 += __shfl_down_sync(0xffffffffu, q2, sh);
        }
        if ((tid & 31) == 0) {
            atomicAdd(&bsum[to], s);
            atomicAdd(&bsum[16 + to], q2);
        }
    }
    __syncthreads();
    if (tid < 32) atomicAdd(&g_sums[tid], bsum[tid]);
}

// ---------------- K4: finalize BN stats ----------------------------------------
__global__ void k_stats() {
    int t = threadIdx.x;
    if (t < 16) {
        float n = 245760.f;
        float mean = g_sums[t] / n;
        float var = g_sums[16 + t] / n - mean * mean;
        g_stats[t] = mean;
        g_stats[16 + t] = rsqrtf(var + 1e-5f);
    }
}

// ---------------- K5: normalize + affine + relu (in place) ----------------------
__global__ void k_bn(float* __restrict__ out, const float* __restrict__ bn_g,
                     const float* __restrict__ bn_b) {
    int i4 = blockIdx.x * 256 + threadIdx.x;   // < 983040 float4s
    int ch = (i4 / 30720) & 15;
    float mean = g_stats[ch], inv = g_stats[16 + ch];
    float gg = bn_g[ch] * inv;
    float bb = bn_b[ch] - mean * gg;
    float4 v = ((float4*)out)[i4];
    v.x = fmaxf(v.x * gg + bb, 0.f);
    v.y = fmaxf(v.y * gg + bb, 0.f);
    v.z = fmaxf(v.z * gg + bb, 0.f);
    v.w = fmaxf(v.w * gg + bb, 0.f);
    ((float4*)out)[i4] = v;
}

// ---------------- launch --------------------------------------------------------
extern "C" void kernel_launch(void* const* d_in, const int* in_sizes, int n_in,
                              void* d_out, int out_size) {
    const float* x      = (const float*)d_in[0];
    const float* p_w    = (const float*)d_in[1];
    const float* p_b    = (const float*)d_in[2];
    const float* m_w    = (const float*)d_in[3];
    const float* m_b    = (const float*)d_in[4];
    const float* conv_w = (const float*)d_in[5];
    const float* comp_w = (const float*)d_in[6];
    const float* spec_w = (const float*)d_in[7];
    const float* bn_g   = (const float*)d_in[8];
    const float* bn_b   = (const float*)d_in[9];
    float* out = (float*)d_out;

    const int SM_K1 = CTS * CTS * XSTR * 4 + 9 * 27 * 32 * 4;   // 197568
    const int SM_K2 = DTS * DTS * XSTR * 4 + 9 * 30 * 32 * 4;   // 221184
    cudaFuncSetAttribute(k_conv1, cudaFuncAttributeMaxDynamicSharedMemorySize, SM_K1);
    cudaFuncSetAttribute(k_deform, cudaFuncAttributeMaxDynamicSharedMemorySize, SM_K2);

    k_prep<<<65, 256>>>(comp_w, conv_w, p_w, m_w);
    k_transpose<<<512, 256>>>(x);
    k_conv1<<<128, 512, SM_K1>>>(p_b, m_b);
    k_deform<<<128, 512, SM_K2>>>();
    k_spec<<<960, 256>>>(spec_w, out);
    k_stats<<<1, 32>>>();
    k_bn<<<3840, 256>>>(out, bn_g, bn_b);
    (void)in_sizes; (void)n_in; (void)out_size;
}

// round 7
// speedup vs baseline: 1.9904x; 1.0579x over previous
#include <cuda_runtime.h>
#include <math.h>

// Shapes: B=2, T=16, C=30, H=W=64.  NIMG = B*T = 32 images, NPIX = 4096.
// Deform conv input is the reshape-scrambled view xr[j][c'] with
//   f1 = j*30+c', b = f1/480, c = (f1%480)/16, t = f1%16  ->  x[b][t][c].
// Output reshape is NOT scrambled: y1[j][o] -> (b=j/16, t=j%16, c=o).

#define NIMG 32
#define NPIX 4096
#define CPAD 32
#define XSTR 36   // smem per-pixel stride (floats): 9 float4s -> all 8 bank groups hit.

typedef unsigned long long ull;

// packed-pair FMA: d.lo += a.lo*b.lo, d.hi += a.hi*b.hi  (sm_100a f32x2)
#define FMA2(d, a, b) asm("fma.rn.f32x2 %0, %1, %2, %0;" : "+l"(d) : "l"(a), "l"(b))

__device__ __forceinline__ ull bc2(float x) {
    ull r;
    asm("mov.b64 %0, {%1, %1};" : "=l"(r) : "r"(__float_as_uint(x)));
    return r;
}
__device__ __forceinline__ float lo2(ull v) { return __uint_as_float((unsigned)v); }
__device__ __forceinline__ float hi2(ull v) { return __uint_as_float((unsigned)(v >> 32)); }

// ---------------- scratch (device globals; no runtime allocation) -------------
__device__ __align__(16) float g_xr[NIMG * NPIX * CPAD];   // NHWC pad-32, 64 MB
__device__ float g_om[NIMG * 28 * NPIX];                   // offsets(18)+mask(9), ch-major
__device__ float g_y1[NIMG * 30 * NPIX];                   // deform+comp output
// packed weights: rows indexed by absolute channel c, outputs consecutive (pairs)
__device__ __align__(16) float g_Wc2[9 * 32 * 32];         // [tap][c][o] o-padded to 32
__device__ __align__(16) float g_Wk2[9 * 32 * 28];         // [tap][c][o] o-padded to 28
__device__ float g_sums[32];                               // BN sum / sumsq per channel
__device__ float g_stats[32];                              // mean / inv_std

// ---------------- K0: weight prep + zero stats --------------------------------
__global__ void k_prep(const float* __restrict__ comp_w, const float* __restrict__ conv_w,
                       const float* __restrict__ p_w, const float* __restrict__ m_w) {
    int t = blockIdx.x * blockDim.x + threadIdx.x;
    const int NW2C = 9 * 32 * 32;          // 9216
    const int NW2K = 9 * 32 * 28;          // 8064
    if (t < NW2C) {
        int n = t >> 10;
        int r = t & 1023;
        int c = r >> 5;
        int o = r & 31;
        float acc = 0.f;
        if (c < 30 && o < 30) {
            for (int m = 0; m < 90; m++)
                acc += comp_w[o * 90 + m] * conv_w[(m * 30 + c) * 9 + n];
        }
        g_Wc2[t] = acc;
    } else if (t < NW2C + NW2K) {
        int u = t - NW2C;
        int n = u / 896;
        int r = u - n * 896;
        int c = r / 28;
        int o = r - c * 28;
        float v = 0.f;
        if (c < 30) {
            if (o < 18)      v = p_w[(o * 30 + c) * 9 + n];
            else if (o < 27) v = m_w[((o - 18) * 30 + c) * 9 + n];
        }
        g_Wk2[u] = v;
    } else if (t < NW2C + NW2K + 32) {
        g_sums[t - (NW2C + NW2K)] = 0.f;
    }
}

// ---------------- Kt: build NHWC pad-32 scrambled view -------------------------
__global__ void k_transpose(const float* __restrict__ x) {
    int t = blockIdx.x * blockDim.x + threadIdx.x;   // 131072 = NIMG*NPIX
    int j = t >> 12;
    int hw = t & 4095;
    float v[CPAD];
#pragma unroll
    for (int cp = 0; cp < 30; cp++) {
        int f1 = j * 30 + cp;
        int b = (f1 >= 480) ? 1 : 0;
        int rem = f1 - b * 480;
        int c = rem >> 4;
        int tt = rem & 15;
        v[cp] = x[((size_t)((b * 16 + tt) * 30 + c)) * NPIX + hw];
    }
    v[30] = 0.f; v[31] = 0.f;
    float4* dst = (float4*)(g_xr + (size_t)t * CPAD);
#pragma unroll
    for (int q = 0; q < 8; q++)
        dst[q] = make_float4(v[4 * q], v[4 * q + 1], v[4 * q + 2], v[4 * q + 3]);
}

// ---------------- K1: offset + mask 3x3 convs (P=2, f32x2 matvec) ---------------
#define CTS 34
__global__ void __launch_bounds__(512, 1) k_conv1(const float* __restrict__ p_b,
                                                  const float* __restrict__ m_b) {
    extern __shared__ float sm[];
    float* xt = sm;                        // [CTS*CTS*XSTR]
    float* wt = sm + CTS * CTS * XSTR;     // [9*32*28]
    int blk = blockIdx.x;
    int j = blk >> 2;
    int tile = blk & 3;
    int th0 = (tile >> 1) << 5;
    int tw0 = (tile & 1) << 5;
    int tid = threadIdx.x;

    for (int pos = tid; pos < CTS * CTS; pos += 512) {
        int rr = pos / CTS, cc = pos % CTS;
        int ih = th0 - 1 + rr, iw = tw0 - 1 + cc;
        float4* d = (float4*)(xt + pos * XSTR);
        if (ih >= 0 && ih < 64 && iw >= 0 && iw < 64) {
            const float4* s = (const float4*)(g_xr + (size_t)(j * NPIX + ih * 64 + iw) * CPAD);
#pragma unroll
            for (int q = 0; q < 8; q++) d[q] = s[q];
        } else {
#pragma unroll
            for (int q = 0; q < 8; q++) d[q] = make_float4(0.f, 0.f, 0.f, 0.f);
        }
    }
    for (int p = tid; p < 9 * 32 * 28 / 4; p += 512)
        ((float4*)wt)[p] = ((const float4*)g_Wk2)[p];
    __syncthreads();

    int tx = tid & 31, ty = tid >> 5;      // ty 0..15
    int h0 = th0 + ty;
    int w = tw0 + tx;
    ull A0[14], A1[14];
#pragma unroll
    for (int op = 0; op < 14; op++) { A0[op] = 0ull; A1[op] = 0ull; }

    for (int n = 0; n < 9; n++) {
        int i = n / 3;
        int jj = n - i * 3;
        const float* b0 = xt + ((ty + i) * CTS + (tx + jj)) * XSTR;
        const float* b1 = b0 + 16 * CTS * XSTR;
        const float* wn = wt + n * 32 * 28;
#pragma unroll
        for (int half = 0; half < 2; half++) {
            int co = half << 4;
            float4 sA[4], sB[4];
            const float4* p0 = (const float4*)(b0 + co);
            const float4* p1 = (const float4*)(b1 + co);
#pragma unroll
            for (int q = 0; q < 4; q++) { sA[q] = p0[q]; sB[q] = p1[q]; }
#pragma unroll
            for (int i4 = 0; i4 < 4; i4++) {
                float4 va = sA[i4], vb = sB[i4];
#pragma unroll
                for (int comp = 0; comp < 4; comp++) {
                    float fa = comp == 0 ? va.x : comp == 1 ? va.y : comp == 2 ? va.z : va.w;
                    float fb = comp == 0 ? vb.x : comp == 1 ? vb.y : comp == 2 ? vb.z : vb.w;
                    int c = co + (i4 << 2) + comp;
                    ull ba = bc2(fa), bb = bc2(fb);
                    const ulonglong2* wc2 = (const ulonglong2*)(wn + c * 28);
#pragma unroll
                    for (int k = 0; k < 7; k++) {
                        ulonglong2 wv = wc2[k];
                        FMA2(A0[2 * k],     wv.x, ba);
                        FMA2(A0[2 * k + 1], wv.y, ba);
                        FMA2(A1[2 * k],     wv.x, bb);
                        FMA2(A1[2 * k + 1], wv.y, bb);
                    }
                }
            }
        }
    }
    float acc0[28], acc1[28];
#pragma unroll
    for (int op = 0; op < 14; op++) {
        acc0[2 * op] = lo2(A0[op]); acc0[2 * op + 1] = hi2(A0[op]);
        acc1[2 * op] = lo2(A1[op]); acc1[2 * op + 1] = hi2(A1[op]);
    }
    int hw0 = h0 * 64 + w;
    size_t ob0 = (size_t)j * 28 * NPIX + hw0;
    size_t ob1 = ob0 + 16 * 64;
#pragma unroll
    for (int o = 0; o < 18; o++) {
        g_om[ob0 + (size_t)o * NPIX] = acc0[o] + p_b[o];
        g_om[ob1 + (size_t)o * NPIX] = acc1[o] + p_b[o];
    }
#pragma unroll
    for (int o = 18; o < 27; o++) {
        float z0 = acc0[o] + m_b[o - 18];
        float z1 = acc1[o] + m_b[o - 18];
        g_om[ob0 + (size_t)o * NPIX] = 1.f / (1.f + expf(-z0));
        g_om[ob1 + (size_t)o * NPIX] = 1.f / (1.f + expf(-z1));
    }
}

// ---------------- K2: fused deform sample + matvec (P=2, f32x2) -----------------
#define DTS 36
__device__ __forceinline__ void add_corner_g(float4* s, const float* base,
                                             int qx, int qy, float g, int co) {
    if (qx >= 1 && qx <= 64 && qy >= 1 && qy <= 64) {
        const float4* p = (const float4*)(base + (size_t)((qx - 1) * 64 + (qy - 1)) * CPAD + co);
#pragma unroll
        for (int q = 0; q < 4; q++) {
            float4 v = p[q];
            s[q].x += g * v.x; s[q].y += g * v.y;
            s[q].z += g * v.z; s[q].w += g * v.w;
        }
    }
}

__global__ void __launch_bounds__(512, 1) k_deform() {
    extern __shared__ float sm[];
    float* xt = sm;                        // [DTS*DTS*XSTR]
    float* wt = sm + DTS * DTS * XSTR;     // [9*32*32]
    int blk = blockIdx.x;
    int j = blk >> 2;
    int tile = blk & 3;
    int th0 = (tile >> 1) << 5;
    int tw0 = (tile & 1) << 5;
    int tx0 = th0 - 1;   // padded coord of smem row 0
    int ty0 = tw0 - 1;
    int tid = threadIdx.x;

    for (int pos = tid; pos < DTS * DTS; pos += 512) {
        int rr = pos / DTS, cc = pos % DTS;
        int qx = tx0 + rr, qy = ty0 + cc;
        float4* d = (float4*)(xt + pos * XSTR);
        if (qx >= 1 && qx <= 64 && qy >= 1 && qy <= 64) {
            const float4* s = (const float4*)(g_xr + (size_t)(j * NPIX + (qx - 1) * 64 + (qy - 1)) * CPAD);
#pragma unroll
            for (int q = 0; q < 8; q++) d[q] = s[q];
        } else {
#pragma unroll
            for (int q = 0; q < 8; q++) d[q] = make_float4(0.f, 0.f, 0.f, 0.f);
        }
    }
    for (int p = tid; p < 9 * 32 * 32 / 4; p += 512)
        ((float4*)wt)[p] = ((const float4*)g_Wc2)[p];
    __syncthreads();

    int tx = tid & 31, ty = tid >> 5;      // ty 0..15
    int h0 = th0 + ty, h1 = h0 + 16;
    int w = tw0 + tx;
    const float* om0 = g_om + (size_t)j * 28 * NPIX + h0 * 64 + w;
    const float* om1 = om0 + 16 * 64;
    const float* gb = g_xr + (size_t)j * NPIX * CPAD;

    ull A0[15], A1[15];
#pragma unroll
    for (int op = 0; op < 15; op++) { A0[op] = 0ull; A1[op] = 0ull; }

    for (int n = 0; n < 9; n++) {
        int dxi = n / 3;
        int dyi = n - dxi * 3;
        const float* wn = wt + n * 32 * 32;

        // ---- pixel 0 geometry ----
        float ox0 = om0[(size_t)n * NPIX];
        float oy0 = om0[(size_t)(9 + n) * NPIX];
        float mk0 = om0[(size_t)(18 + n) * NPIX];
        float px0 = (float)(h0 + dxi) + ox0;
        float py0 = (float)(w + dyi) + oy0;
        float qfx0 = floorf(px0), qfy0 = floorf(py0);
        float lx0 = fminf(fmaxf(qfx0, 0.f), 65.f);
        float ly0 = fminf(fmaxf(qfy0, 0.f), 65.f);
        float rx0 = fminf(fmaxf(qfx0 + 1.f, 0.f), 65.f);
        float ry0 = fminf(fmaxf(qfy0 + 1.f, 0.f), 65.f);
        float pxc0 = fminf(fmaxf(px0, 0.f), 65.f);
        float pyc0 = fminf(fmaxf(py0, 0.f), 65.f);
        float gxl0 = 1.f + lx0 - pxc0, gxr0 = 1.f - rx0 + pxc0;
        float gyl0 = 1.f + ly0 - pyc0, gyr0 = 1.f - ry0 + pyc0;
        float g0lt = gxl0 * gyl0 * mk0, g0rb = gxr0 * gyr0 * mk0;
        float g0lb = gxl0 * gyr0 * mk0, g0rt = gxr0 * gyl0 * mk0;
        int a0x = (int)lx0, a0y = (int)ly0, b0x = (int)rx0, b0y = (int)ry0;
        bool f0 = (a0x >= tx0) & (b0x < tx0 + DTS) & (a0y >= ty0) & (b0y < ty0 + DTS);

        // ---- pixel 1 geometry ----
        float ox1 = om1[(size_t)n * NPIX];
        float oy1 = om1[(size_t)(9 + n) * NPIX];
        float mk1 = om1[(size_t)(18 + n) * NPIX];
        float px1 = (float)(h1 + dxi) + ox1;
        float py1 = (float)(w + dyi) + oy1;
        float qfx1 = floorf(px1), qfy1 = floorf(py1);
        float lx1 = fminf(fmaxf(qfx1, 0.f), 65.f);
        float ly1 = fminf(fmaxf(qfy1, 0.f), 65.f);
        float rx1 = fminf(fmaxf(qfx1 + 1.f, 0.f), 65.f);
        float ry1 = fminf(fmaxf(qfy1 + 1.f, 0.f), 65.f);
        float pxc1 = fminf(fmaxf(px1, 0.f), 65.f);
        float pyc1 = fminf(fmaxf(py1, 0.f), 65.f);
        float gxl1 = 1.f + lx1 - pxc1, gxr1 = 1.f - rx1 + pxc1;
        float gyl1 = 1.f + ly1 - pyc1, gyr1 = 1.f - ry1 + pyc1;
        float g1lt = gxl1 * gyl1 * mk1, g1rb = gxr1 * gyr1 * mk1;
        float g1lb = gxl1 * gyr1 * mk1, g1rt = gxr1 * gyl1 * mk1;
        int a1x = (int)lx1, a1y = (int)ly1, b1x = (int)rx1, b1y = (int)ry1;
        bool f1 = (a1x >= tx0) & (b1x < tx0 + DTS) & (a1y >= ty0) & (b1y < ty0 + DTS);

#pragma unroll
        for (int half = 0; half < 2; half++) {
            int co = half << 4;
            float4 sA[4], sB[4];

            if (f0) {
                const float4* A = (const float4*)(xt + ((a0x - tx0) * DTS + (a0y - ty0)) * XSTR + co);
                const float4* B = (const float4*)(xt + ((b0x - tx0) * DTS + (b0y - ty0)) * XSTR + co);
                const float4* C = (const float4*)(xt + ((a0x - tx0) * DTS + (b0y - ty0)) * XSTR + co);
                const float4* D = (const float4*)(xt + ((b0x - tx0) * DTS + (a0y - ty0)) * XSTR + co);
#pragma unroll
                for (int q = 0; q < 4; q++) {
                    float4 a = A[q], b = B[q], c = C[q], d = D[q];
                    sA[q].x = g0lt * a.x + g0rb * b.x + g0lb * c.x + g0rt * d.x;
                    sA[q].y = g0lt * a.y + g0rb * b.y + g0lb * c.y + g0rt * d.y;
                    sA[q].z = g0lt * a.z + g0rb * b.z + g0lb * c.z + g0rt * d.z;
                    sA[q].w = g0lt * a.w + g0rb * b.w + g0lb * c.w + g0rt * d.w;
                }
            } else {
#pragma unroll
                for (int q = 0; q < 4; q++) sA[q] = make_float4(0.f, 0.f, 0.f, 0.f);
                add_corner_g(sA, gb, a0x, a0y, g0lt, co);
                add_corner_g(sA, gb, b0x, b0y, g0rb, co);
                add_corner_g(sA, gb, a0x, b0y, g0lb, co);
                add_corner_g(sA, gb, b0x, a0y, g0rt, co);
            }

            if (f1) {
                const float4* A = (const float4*)(xt + ((a1x - tx0) * DTS + (a1y - ty0)) * XSTR + co);
                const float4* B = (const float4*)(xt + ((b1x - tx0) * DTS + (b1y - ty0)) * XSTR + co);
                const float4* C = (const float4*)(xt + ((a1x - tx0) * DTS + (b1y - ty0)) * XSTR + co);
                const float4* D = (const float4*)(xt + ((b1x - tx0) * DTS + (a1y - ty0)) * XSTR + co);
#pragma unroll
                for (int q = 0; q < 4; q++) {
                    float4 a = A[q], b = B[q], c = C[q], d = D[q];
                    sB[q].x = g1lt * a.x + g1rb * b.x + g1lb * c.x + g1rt * d.x;
                    sB[q].y = g1lt * a.y + g1rb * b.y + g1lb * c.y + g1rt * d.y;
                    sB[q].z = g1lt * a.z + g1rb * b.z + g1lb * c.z + g1rt * d.z;
                    sB[q].w = g1lt * a.w + g1rb * b.w + g1lb * c.w + g1rt * d.w;
                }
            } else {
#pragma unroll
                for (int q = 0; q < 4; q++) sB[q] = make_float4(0.f, 0.f, 0.f, 0.f);
                add_corner_g(sB, gb, a1x, a1y, g1lt, co);
                add_corner_g(sB, gb, b1x, b1y, g1rb, co);
                add_corner_g(sB, gb, a1x, b1y, g1lb, co);
                add_corner_g(sB, gb, b1x, a1y, g1rt, co);
            }

#pragma unroll
            for (int i4 = 0; i4 < 4; i4++) {
                float4 va = sA[i4], vb = sB[i4];
#pragma unroll
                for (int comp = 0; comp < 4; comp++) {
                    float fa = comp == 0 ? va.x : comp == 1 ? va.y : comp == 2 ? va.z : va.w;
                    float fb = comp == 0 ? vb.x : comp == 1 ? vb.y : comp == 2 ? vb.z : vb.w;
                    int c = co + (i4 << 2) + comp;
                    ull ba = bc2(fa), bb = bc2(fb);
                    const float* wrow = wn + c * 32;
                    const ulonglong2* wc2 = (const ulonglong2*)wrow;
#pragma unroll
                    for (int k = 0; k < 7; k++) {
                        ulonglong2 wv = wc2[k];
                        FMA2(A0[2 * k],     wv.x, ba);
                        FMA2(A0[2 * k + 1], wv.y, ba);
                        FMA2(A1[2 * k],     wv.x, bb);
                        FMA2(A1[2 * k + 1], wv.y, bb);
                    }
                    ull w14 = *(const ull*)(wrow + 28);   // pair (o=28,29)
                    FMA2(A0[14], w14, ba);
                    FMA2(A1[14], w14, bb);
                }
            }
        }
    }

    float acc0[30], acc1[30];
#pragma unroll
    for (int op = 0; op < 15; op++) {
        acc0[2 * op] = lo2(A0[op]); acc0[2 * op + 1] = hi2(A0[op]);
        acc1[2 * op] = lo2(A1[op]); acc1[2 * op + 1] = hi2(A1[op]);
    }
    int hw0 = h0 * 64 + w;
    float* yb0 = g_y1 + (size_t)j * 30 * NPIX + hw0;
    float* yb1 = yb0 + 16 * 64;
#pragma unroll
    for (int o = 0; o < 30; o++) {
        yb0[(size_t)o * NPIX] = acc0[o];
        yb1[(size_t)o * NPIX] = acc1[o];
    }
}

// ---------------- K3: spec (temporal/depth) conv + BN partial sums --------------
__global__ void k_spec(const float* __restrict__ spec_w, float* __restrict__ out) {
    __shared__ float sw[16 * 48];
    __shared__ float bsum[32];
    int tid = threadIdx.x;
    for (int p = tid; p < 768; p += 256) sw[p] = spec_w[p];
    if (tid < 32) bsum[tid] = 0.f;
    __syncthreads();

    int idx = blockIdx.x * 256 + tid;        // < 245760 = 2*30*4096
    int b = idx / (30 * NPIX);
    int r = idx - b * (30 * NPIX);
    int d = r >> 12;
    int hw = r & 4095;

    float v[48];
#pragma unroll
    for (int ti = 0; ti < 16; ti++) {
#pragma unroll
        for (int kd = 0; kd < 3; kd++) {
            int dd = d + kd - 1;
            v[ti * 3 + kd] = (dd >= 0 && dd < 30)
                ? g_y1[((size_t)(b * 16 + ti) * 30 + dd) * NPIX + hw] : 0.f;
        }
    }
#pragma unroll
    for (int to = 0; to < 16; to++) {
        const float4* wp = (const float4*)(sw + to * 48);
        float a0 = 0.f, a1 = 0.f, a2 = 0.f, a3 = 0.f;
#pragma unroll
        for (int q = 0; q < 12; q++) {
            float4 wv = wp[q];
            a0 += wv.x * v[4 * q];     a1 += wv.y * v[4 * q + 1];
            a2 += wv.z * v[4 * q + 2]; a3 += wv.w * v[4 * q + 3];
        }
        float o = (a0 + a1) + (a2 + a3);
        out[((size_t)(b * 16 + to) * 30 + d) * NPIX + hw] = o;

        float s = o, q2 = o * o;
#pragma unroll
        for (int sh = 16; sh >= 1; sh >>= 1) {
            s  += __shfl_down_sync(0xffffffffu, s, sh);
            q2 += __shfl_down_sync(0xffffffffu, q2, sh);
        }
        if ((tid & 31) == 0) {
            atomicAdd(&bsum[to], s);
            atomicAdd(&bsum[16 + to], q2);
        }
    }
    __syncthreads();
    if (tid < 32) atomicAdd(&g_sums[tid], bsum[tid]);
}

// ---------------- K4: finalize BN stats ----------------------------------------
__global__ void k_stats() {
    int t = threadIdx.x;
    if (t < 16) {
        float n = 245760.f;
        float mean = g_sums[t] / n;
        float var = g_sums[16 + t] / n - mean * mean;
        g_stats[t] = mean;
        g_stats[16 + t] = rsqrtf(var + 1e-5f);
    }
}

// ---------------- K5: normalize + affine + relu (in place) ----------------------
__global__ void k_bn(float* __restrict__ out, const float* __restrict__ bn_g,
                     const float* __restrict__ bn_b) {
    int i4 = blockIdx.x * 256 + threadIdx.x;   // < 983040 float4s
    int ch = (i4 / 30720) & 15;
    float mean = g_stats[ch], inv = g_stats[16 + ch];
    float gg = bn_g[ch] * inv;
    float bb = bn_b[ch] - mean * gg;
    float4 v = ((float4*)out)[i4];
    v.x = fmaxf(v.x * gg + bb, 0.f);
    v.y = fmaxf(v.y * gg + bb, 0.f);
    v.z = fmaxf(v.z * gg + bb, 0.f);
    v.w = fmaxf(v.w * gg + bb, 0.f);
    ((float4*)out)[i4] = v;
}

// ---------------- launch --------------------------------------------------------
extern "C" void kernel_launch(void* const* d_in, const int* in_sizes, int n_in,
                              void* d_out, int out_size) {
    const float* x      = (const float*)d_in[0];
    const float* p_w    = (const float*)d_in[1];
    const float* p_b    = (const float*)d_in[2];
    const float* m_w    = (const float*)d_in[3];
    const float* m_b    = (const float*)d_in[4];
    const float* conv_w = (const float*)d_in[5];
    const float* comp_w = (const float*)d_in[6];
    const float* spec_w = (const float*)d_in[7];
    const float* bn_g   = (const float*)d_in[8];
    const float* bn_b   = (const float*)d_in[9];
    float* out = (float*)d_out;

    const int SM_K1 = CTS * CTS * XSTR * 4 + 9 * 32 * 28 * 4;   // 198720
    const int SM_K2 = DTS * DTS * XSTR * 4 + 9 * 32 * 32 * 4;   // 223488
    cudaFuncSetAttribute(k_conv1, cudaFuncAttributeMaxDynamicSharedMemorySize, SM_K1);
    cudaFuncSetAttribute(k_deform, cudaFuncAttributeMaxDynamicSharedMemorySize, SM_K2);

    k_prep<<<68, 256>>>(comp_w, conv_w, p_w, m_w);
    k_transpose<<<512, 256>>>(x);
    k_conv1<<<128, 512, SM_K1>>>(p_b, m_b);
    k_deform<<<128, 512, SM_K2>>>();
    k_spec<<<960, 256>>>(spec_w, out);
    k_stats<<<1, 32>>>();
    k_bn<<<3840, 256>>>(out, bn_g, bn_b);
    (void)in_sizes; (void)n_in; (void)out_size;
}

// round 9
// speedup vs baseline: 2.1479x; 1.0791x over previous
#include <cuda_runtime.h>
#include <math.h>

// Shapes: B=2, T=16, C=30, H=W=64.  NIMG = B*T = 32 images, NPIX = 4096.
// Deform conv input is the reshape-scrambled view xr[j][c'] with
//   f1 = j*30+c', b = f1/480, c = (f1%480)/16, t = f1%16  ->  x[b][t][c].
// Tiles are gathered directly from x (no transposed copy).
// Output reshape is NOT scrambled: y1[j][o] -> (b=j/16, t=j%16, c=o).

#define NIMG 32
#define NPIX 4096
#define XSTR 36   // smem per-pixel stride (floats): 9 float4s -> all 8 bank groups hit.

typedef unsigned long long ull;

// packed-pair FMA: d.lo += a.lo*b.lo, d.hi += a.hi*b.hi  (sm_100a f32x2)
#define FMA2(d, a, b) asm("fma.rn.f32x2 %0, %1, %2, %0;" : "+l"(d) : "l"(a), "l"(b))

__device__ __forceinline__ ull bc2(float x) {
    ull r;
    asm("mov.b64 %0, {%1, %1};" : "=l"(r) : "r"(__float_as_uint(x)));
    return r;
}
__device__ __forceinline__ float lo2(ull v) { return __uint_as_float((unsigned)v); }
__device__ __forceinline__ float hi2(ull v) { return __uint_as_float((unsigned)(v >> 32)); }

// plane offset of scrambled channel cp for image j:  x[b][t][c] plane base
__device__ __forceinline__ int plane_off(int j, int cp) {
    int f1 = j * 30 + cp;
    int b = (f1 >= 480) ? 1 : 0;
    int rem = f1 - b * 480;
    int c = rem >> 4;
    int tt = rem & 15;
    return ((b * 16 + tt) * 30 + c) * NPIX;
}

// ---------------- scratch (device globals; no runtime allocation) -------------
__device__ float g_om[NIMG * 28 * NPIX];                   // offsets(18)+mask(9), ch-major
__device__ float g_y1[NIMG * 30 * NPIX];                   // deform+comp output
// packed weights: rows indexed by absolute channel c, outputs consecutive (pairs)
__device__ __align__(16) float g_Wc2[9 * 32 * 32];         // [tap][c][o] o-padded to 32
__device__ __align__(16) float g_Wk2[9 * 32 * 28];         // [tap][c][o] o-padded to 28
__device__ float g_sums[32];                               // BN sum / sumsq per channel
__device__ float g_stats[32];                              // mean / inv_std

// ---------------- K0: weight prep + zero stats --------------------------------
__global__ void k_prep(const float* __restrict__ comp_w, const float* __restrict__ conv_w,
                       const float* __restrict__ p_w, const float* __restrict__ m_w) {
    int t = blockIdx.x * blockDim.x + threadIdx.x;
    const int NW2C = 9 * 32 * 32;          // 9216
    const int NW2K = 9 * 32 * 28;          // 8064
    if (t < NW2C) {
        int n = t >> 10;
        int r = t & 1023;
        int c = r >> 5;
        int o = r & 31;
        float acc = 0.f;
        if (c < 30 && o < 30) {
            for (int m = 0; m < 90; m++)
                acc += comp_w[o * 90 + m] * conv_w[(m * 30 + c) * 9 + n];
        }
        g_Wc2[t] = acc;
    } else if (t < NW2C + NW2K) {
        int u = t - NW2C;
        int n = u / 896;
        int r = u - n * 896;
        int c = r / 28;
        int o = r - c * 28;
        float v = 0.f;
        if (c < 30) {
            if (o < 18)      v = p_w[(o * 30 + c) * 9 + n];
            else if (o < 27) v = m_w[((o - 18) * 30 + c) * 9 + n];
        }
        g_Wk2[u] = v;
    } else if (t < NW2C + NW2K + 32) {
        g_sums[t - (NW2C + NW2K)] = 0.f;
    }
}

// ---------------- K1: offset + mask 3x3 convs (P=2, f32x2 matvec) ---------------
#define CTS 34
__global__ void __launch_bounds__(512, 1) k_conv1(const float* __restrict__ x,
                                                  const float* __restrict__ p_b,
                                                  const float* __restrict__ m_b) {
    extern __shared__ float sm[];
    float* xt = sm;                        // [CTS*CTS*XSTR]
    float* wt = sm + CTS * CTS * XSTR;     // [9*32*28]
    int* po = (int*)(wt + 9 * 32 * 28);    // [32] scrambled plane offsets
    int blk = blockIdx.x;
    int j = blk >> 2;
    int tile = blk & 3;
    int th0 = (tile >> 1) << 5;
    int tw0 = (tile & 1) << 5;
    int tid = threadIdx.x;

    if (tid < 32) po[tid] = (tid < 30) ? plane_off(j, tid) : 0;
    __syncthreads();

    for (int pos = tid; pos < CTS * CTS; pos += 512) {
        int rr = pos / CTS, cc = pos % CTS;
        int ih = th0 - 1 + rr, iw = tw0 - 1 + cc;
        float v[32];
        if (ih >= 0 && ih < 64 && iw >= 0 && iw < 64) {
            int hw = ih * 64 + iw;
#pragma unroll
            for (int cp = 0; cp < 30; cp++) v[cp] = x[po[cp] + hw];
        } else {
#pragma unroll
            for (int cp = 0; cp < 30; cp++) v[cp] = 0.f;
        }
        v[30] = 0.f; v[31] = 0.f;
        float4* d = (float4*)(xt + pos * XSTR);
#pragma unroll
        for (int q = 0; q < 8; q++)
            d[q] = make_float4(v[4 * q], v[4 * q + 1], v[4 * q + 2], v[4 * q + 3]);
    }
    for (int p = tid; p < 9 * 32 * 28 / 4; p += 512)
        ((float4*)wt)[p] = ((const float4*)g_Wk2)[p];
    __syncthreads();

    int tx = tid & 31, ty = tid >> 5;      // ty 0..15
    int h0 = th0 + ty;
    int w = tw0 + tx;
    ull A0[14], A1[14];
#pragma unroll
    for (int op = 0; op < 14; op++) { A0[op] = 0ull; A1[op] = 0ull; }

    for (int n = 0; n < 9; n++) {
        int i = n / 3;
        int jj = n - i * 3;
        const float* b0 = xt + ((ty + i) * CTS + (tx + jj)) * XSTR;
        const float* b1 = b0 + 16 * CTS * XSTR;
        const float* wn = wt + n * 32 * 28;
#pragma unroll
        for (int half = 0; half < 2; half++) {
            int co = half << 4;
            float4 sA[4], sB[4];
            const float4* p0 = (const float4*)(b0 + co);
            const float4* p1 = (const float4*)(b1 + co);
#pragma unroll
            for (int q = 0; q < 4; q++) { sA[q] = p0[q]; sB[q] = p1[q]; }
#pragma unroll
            for (int i4 = 0; i4 < 4; i4++) {
                float4 va = sA[i4], vb = sB[i4];
#pragma unroll
                for (int comp = 0; comp < 4; comp++) {
                    float fa = comp == 0 ? va.x : comp == 1 ? va.y : comp == 2 ? va.z : va.w;
                    float fb = comp == 0 ? vb.x : comp == 1 ? vb.y : comp == 2 ? vb.z : vb.w;
                    int c = co + (i4 << 2) + comp;
                    ull ba = bc2(fa), bb = bc2(fb);
                    const ulonglong2* wc2 = (const ulonglong2*)(wn + c * 28);
#pragma unroll
                    for (int k = 0; k < 7; k++) {
                        ulonglong2 wv = wc2[k];
                        FMA2(A0[2 * k],     wv.x, ba);
                        FMA2(A0[2 * k + 1], wv.y, ba);
                        FMA2(A1[2 * k],     wv.x, bb);
                        FMA2(A1[2 * k + 1], wv.y, bb);
                    }
                }
            }
        }
    }
    float acc0[28], acc1[28];
#pragma unroll
    for (int op = 0; op < 14; op++) {
        acc0[2 * op] = lo2(A0[op]); acc0[2 * op + 1] = hi2(A0[op]);
        acc1[2 * op] = lo2(A1[op]); acc1[2 * op + 1] = hi2(A1[op]);
    }
    int hw0 = h0 * 64 + w;
    size_t ob0 = (size_t)j * 28 * NPIX + hw0;
    size_t ob1 = ob0 + 16 * 64;
#pragma unroll
    for (int o = 0; o < 18; o++) {
        g_om[ob0 + (size_t)o * NPIX] = acc0[o] + p_b[o];
        g_om[ob1 + (size_t)o * NPIX] = acc1[o] + p_b[o];
    }
#pragma unroll
    for (int o = 18; o < 27; o++) {
        float z0 = acc0[o] + m_b[o - 18];
        float z1 = acc1[o] + m_b[o - 18];
        g_om[ob0 + (size_t)o * NPIX] = 1.f / (1.f + expf(-z0));
        g_om[ob1 + (size_t)o * NPIX] = 1.f / (1.f + expf(-z1));
    }
}

// ---------------- K2: fused deform sample + matvec (P=2, f32x2) -----------------
#define DTS 36
// cold path: gather corner channels straight from scrambled x.
// Channels >=30 load via po[]=0 (finite garbage) and are killed by zero weights.
__device__ __forceinline__ void add_corner_x(float4* s, const float* __restrict__ x,
                                             const int* po, int qx, int qy,
                                             float g, int co) {
    if (qx >= 1 && qx <= 64 && qy >= 1 && qy <= 64) {
        int hw = (qx - 1) * 64 + (qy - 1);
#pragma unroll
        for (int q = 0; q < 4; q++) {
            int c0 = co + (q << 2);
            float4 v;
            v.x = x[po[c0]     + hw];
            v.y = x[po[c0 + 1] + hw];
            v.z = x[po[c0 + 2] + hw];
            v.w = x[po[c0 + 3] + hw];
            s[q].x += g * v.x; s[q].y += g * v.y;
            s[q].z += g * v.z; s[q].w += g * v.w;
        }
    }
}

__global__ void __launch_bounds__(512, 1) k_deform(const float* __restrict__ x) {
    extern __shared__ float sm[];
    float* xt = sm;                        // [DTS*DTS*XSTR]
    float* wt = sm + DTS * DTS * XSTR;     // [9*32*32]
    int* po = (int*)(wt + 9 * 32 * 32);    // [32]
    int blk = blockIdx.x;
    int j = blk >> 2;
    int tile = blk & 3;
    int th0 = (tile >> 1) << 5;
    int tw0 = (tile & 1) << 5;
    int tx0 = th0 - 1;   // padded coord of smem row 0
    int ty0 = tw0 - 1;
    int tid = threadIdx.x;

    if (tid < 32) po[tid] = (tid < 30) ? plane_off(j, tid) : 0;
    __syncthreads();

    for (int pos = tid; pos < DTS * DTS; pos += 512) {
        int rr = pos / DTS, cc = pos % DTS;
        int qx = tx0 + rr, qy = ty0 + cc;
        float v[32];
        if (qx >= 1 && qx <= 64 && qy >= 1 && qy <= 64) {
            int hw = (qx - 1) * 64 + (qy - 1);
#pragma unroll
            for (int cp = 0; cp < 30; cp++) v[cp] = x[po[cp] + hw];
        } else {
#pragma unroll
            for (int cp = 0; cp < 30; cp++) v[cp] = 0.f;
        }
        v[30] = 0.f; v[31] = 0.f;
        float4* d = (float4*)(xt + pos * XSTR);
#pragma unroll
        for (int q = 0; q < 8; q++)
            d[q] = make_float4(v[4 * q], v[4 * q + 1], v[4 * q + 2], v[4 * q + 3]);
    }
    for (int p = tid; p < 9 * 32 * 32 / 4; p += 512)
        ((float4*)wt)[p] = ((const float4*)g_Wc2)[p];
    __syncthreads();

    int tx = tid & 31, ty = tid >> 5;      // ty 0..15
    int h0 = th0 + ty, h1 = h0 + 16;
    int w = tw0 + tx;
    const float* om0 = g_om + (size_t)j * 28 * NPIX + h0 * 64 + w;
    const float* om1 = om0 + 16 * 64;

    ull A0[15], A1[15];
#pragma unroll
    for (int op = 0; op < 15; op++) { A0[op] = 0ull; A1[op] = 0ull; }

    for (int n = 0; n < 9; n++) {
        int dxi = n / 3;
        int dyi = n - dxi * 3;
        const float* wn = wt + n * 32 * 32;

        // ---- pixel 0 geometry ----
        float ox0 = om0[(size_t)n * NPIX];
        float oy0 = om0[(size_t)(9 + n) * NPIX];
        float mk0 = om0[(size_t)(18 + n) * NPIX];
        float px0 = (float)(h0 + dxi) + ox0;
        float py0 = (float)(w + dyi) + oy0;
        float qfx0 = floorf(px0), qfy0 = floorf(py0);
        float lx0 = fminf(fmaxf(qfx0, 0.f), 65.f);
        float ly0 = fminf(fmaxf(qfy0, 0.f), 65.f);
        float rx0 = fminf(fmaxf(qfx0 + 1.f, 0.f), 65.f);
        float ry0 = fminf(fmaxf(qfy0 + 1.f, 0.f), 65.f);
        float pxc0 = fminf(fmaxf(px0, 0.f), 65.f);
        float pyc0 = fminf(fmaxf(py0, 0.f), 65.f);
        float gxl0 = 1.f + lx0 - pxc0, gxr0 = 1.f - rx0 + pxc0;
        float gyl0 = 1.f + ly0 - pyc0, gyr0 = 1.f - ry0 + pyc0;
        float g0lt = gxl0 * gyl0 * mk0, g0rb = gxr0 * gyr0 * mk0;
        float g0lb = gxl0 * gyr0 * mk0, g0rt = gxr0 * gyl0 * mk0;
        int a0x = (int)lx0, a0y = (int)ly0, b0x = (int)rx0, b0y = (int)ry0;
        bool f0 = (a0x >= tx0) & (b0x < tx0 + DTS) & (a0y >= ty0) & (b0y < ty0 + DTS);

        // ---- pixel 1 geometry ----
        float ox1 = om1[(size_t)n * NPIX];
        float oy1 = om1[(size_t)(9 + n) * NPIX];
        float mk1 = om1[(size_t)(18 + n) * NPIX];
        float px1 = (float)(h1 + dxi) + ox1;
        float py1 = (float)(w + dyi) + oy1;
        float qfx1 = floorf(px1), qfy1 = floorf(py1);
        float lx1 = fminf(fmaxf(qfx1, 0.f), 65.f);
        float ly1 = fminf(fmaxf(qfy1, 0.f), 65.f);
        float rx1 = fminf(fmaxf(qfx1 + 1.f, 0.f), 65.f);
        float ry1 = fminf(fmaxf(qfy1 + 1.f, 0.f), 65.f);
        float pxc1 = fminf(fmaxf(px1, 0.f), 65.f);
        float pyc1 = fminf(fmaxf(py1, 0.f), 65.f);
        float gxl1 = 1.f + lx1 - pxc1, gxr1 = 1.f - rx1 + pxc1;
        float gyl1 = 1.f + ly1 - pyc1, gyr1 = 1.f - ry1 + pyc1;
        float g1lt = gxl1 * gyl1 * mk1, g1rb = gxr1 * gyr1 * mk1;
        float g1lb = gxl1 * gyr1 * mk1, g1rt = gxr1 * gyl1 * mk1;
        int a1x = (int)lx1, a1y = (int)ly1, b1x = (int)rx1, b1y = (int)ry1;
        bool f1 = (a1x >= tx0) & (b1x < tx0 + DTS) & (a1y >= ty0) & (b1y < ty0 + DTS);

#pragma unroll
        for (int half = 0; half < 2; half++) {
            int co = half << 4;
            float4 sA[4], sB[4];

            if (f0) {
                const float4* A = (const float4*)(xt + ((a0x - tx0) * DTS + (a0y - ty0)) * XSTR + co);
                const float4* B = (const float4*)(xt + ((b0x - tx0) * DTS + (b0y - ty0)) * XSTR + co);
                const float4* C = (const float4*)(xt + ((a0x - tx0) * DTS + (b0y - ty0)) * XSTR + co);
                const float4* D = (const float4*)(xt + ((b0x - tx0) * DTS + (a0y - ty0)) * XSTR + co);
#pragma unroll
                for (int q = 0; q < 4; q++) {
                    float4 a = A[q], b = B[q], c = C[q], d = D[q];
                    sA[q].x = g0lt * a.x + g0rb * b.x + g0lb * c.x + g0rt * d.x;
                    sA[q].y = g0lt * a.y + g0rb * b.y + g0lb * c.y + g0rt * d.y;
                    sA[q].z = g0lt * a.z + g0rb * b.z + g0lb * c.z + g0rt * d.z;
                    sA[q].w = g0lt * a.w + g0rb * b.w + g0lb * c.w + g0rt * d.w;
                }
            } else {
#pragma unroll
                for (int q = 0; q < 4; q++) sA[q] = make_float4(0.f, 0.f, 0.f, 0.f);
                add_corner_x(sA, x, po, a0x, a0y, g0lt, co);
                add_corner_x(sA, x, po, b0x, b0y, g0rb, co);
                add_corner_x(sA, x, po, a0x, b0y, g0lb, co);
                add_corner_x(sA, x, po, b0x, a0y, g0rt, co);
            }

            if (f1) {
                const float4* A = (const float4*)(xt + ((a1x - tx0) * DTS + (a1y - ty0)) * XSTR + co);
                const float4* B = (const float4*)(xt + ((b1x - tx0) * DTS + (b1y - ty0)) * XSTR + co);
                const float4* C = (const float4*)(xt + ((a1x - tx0) * DTS + (b1y - ty0)) * XSTR + co);
                const float4* D = (const float4*)(xt + ((b1x - tx0) * DTS + (a1y - ty0)) * XSTR + co);
#pragma unroll
                for (int q = 0; q < 4; q++) {
                    float4 a = A[q], b = B[q], c = C[q], d = D[q];
                    sB[q].x = g1lt * a.x + g1rb * b.x + g1lb * c.x + g1rt * d.x;
                    sB[q].y = g1lt * a.y + g1rb * b.y + g1lb * c.y + g1rt * d.y;
                    sB[q].z = g1lt * a.z + g1rb * b.z + g1lb * c.z + g1rt * d.z;
                    sB[q].w = g1lt * a.w + g1rb * b.w + g1lb * c.w + g1rt * d.w;
                }
            } else {
#pragma unroll
                for (int q = 0; q < 4; q++) sB[q] = make_float4(0.f, 0.f, 0.f, 0.f);
                add_corner_x(sB, x, po, a1x, a1y, g1lt, co);
                add_corner_x(sB, x, po, b1x, b1y, g1rb, co);
                add_corner_x(sB, x, po, a1x, b1y, g1lb, co);
                add_corner_x(sB, x, po, b1x, a1y, g1rt, co);
            }

#pragma unroll
            for (int i4 = 0; i4 < 4; i4++) {
                float4 va = sA[i4], vb = sB[i4];
#pragma unroll
                for (int comp = 0; comp < 4; comp++) {
                    float fa = comp == 0 ? va.x : comp == 1 ? va.y : comp == 2 ? va.z : va.w;
                    float fb = comp == 0 ? vb.x : comp == 1 ? vb.y : comp == 2 ? vb.z : vb.w;
                    int c = co + (i4 << 2) + comp;
                    ull ba = bc2(fa), bb = bc2(fb);
                    const float* wrow = wn + c * 32;
                    const ulonglong2* wc2 = (const ulonglong2*)wrow;
#pragma unroll
                    for (int k = 0; k < 7; k++) {
                        ulonglong2 wv = wc2[k];
                        FMA2(A0[2 * k],     wv.x, ba);
                        FMA2(A0[2 * k + 1], wv.y, ba);
                        FMA2(A1[2 * k],     wv.x, bb);
                        FMA2(A1[2 * k + 1], wv.y, bb);
                    }
                    ull w14 = *(const ull*)(wrow + 28);   // pair (o=28,29)
                    FMA2(A0[14], w14, ba);
                    FMA2(A1[14], w14, bb);
                }
            }
        }
    }

    float acc0[30], acc1[30];
#pragma unroll
    for (int op = 0; op < 15; op++) {
        acc0[2 * op] = lo2(A0[op]); acc0[2 * op + 1] = hi2(A0[op]);
        acc1[2 * op] = lo2(A1[op]); acc1[2 * op + 1] = hi2(A1[op]);
    }
    int hw0 = h0 * 64 + w;
    float* yb0 = g_y1 + (size_t)j * 30 * NPIX + hw0;
    float* yb1 = yb0 + 16 * 64;
#pragma unroll
    for (int o = 0; o < 30; o++) {
        yb0[(size_t)o * NPIX] = acc0[o];
        yb1[(size_t)o * NPIX] = acc1[o];
    }
}

// ---------------- K3: spec conv (f32x2 over output pairs) + BN sums -------------
__global__ void k_spec(const float* __restrict__ spec_w, float* __restrict__ out) {
    __shared__ float sw2[48 * 16];   // transposed: [c=ti*3+kd][to]
    __shared__ float bsum[32];
    int tid = threadIdx.x;
    for (int p = tid; p < 768; p += 256) {
        int to = p / 48, c = p - to * 48;
        sw2[c * 16 + to] = spec_w[p];
    }
    if (tid < 32) bsum[tid] = 0.f;
    __syncthreads();

    int idx = blockIdx.x * 256 + tid;        // < 245760 = 2*30*4096
    int b = idx / (30 * NPIX);
    int r = idx - b * (30 * NPIX);
    int d = r >> 12;
    int hw = r & 4095;

    float v[48];
#pragma unroll
    for (int ti = 0; ti < 16; ti++) {
#pragma unroll
        for (int kd = 0; kd < 3; kd++) {
            int dd = d + kd - 1;
            v[ti * 3 + kd] = (dd >= 0 && dd < 30)
                ? g_y1[((size_t)(b * 16 + ti) * 30 + dd) * NPIX + hw] : 0.f;
        }
    }
    ull A[8];
#pragma unroll
    for (int op = 0; op < 8; op++) A[op] = 0ull;
#pragma unroll
    for (int c = 0; c < 48; c++) {
        ull bv = bc2(v[c]);
        const ulonglong2* wr = (const ulonglong2*)(sw2 + c * 16);
        ulonglong2 w01 = wr[0], w23 = wr[1];
        FMA2(A[0], w01.x, bv); FMA2(A[1], w01.y, bv);
        FMA2(A[2], w23.x, bv); FMA2(A[3], w23.y, bv);
        wr += 2;
        ulonglong2 w45 = wr[0], w67 = wr[1];
        FMA2(A[4], w45.x, bv); FMA2(A[5], w45.y, bv);
        FMA2(A[6], w67.x, bv); FMA2(A[7], w67.y, bv);
    }
#pragma unroll
    for (int to = 0; to < 16; to++) {
        float o = (to & 1) ? hi2(A[to >> 1]) : lo2(A[to >> 1]);
        out[((size_t)(b * 16 + to) * 30 + d) * NPIX + hw] = o;

        float s = o, q2 = o * o;
#pragma unroll
        for (int sh = 16; sh >= 1; sh >>= 1) {
            s  += __shfl_down_sync(0xffffffffu, s, sh);
            q2 += __shfl_down_sync(0xffffffffu, q2, sh);
        }
        if ((tid & 31) == 0) {
            atomicAdd(&bsum[to], s);
            atomicAdd(&bsum[16 + to], q2);
        }
    }
    __syncthreads();
    if (tid < 32) atomicAdd(&g_sums[tid], bsum[tid]);
}

// ---------------- K4: finalize BN stats ----------------------------------------
__global__ void k_stats() {
    int t = threadIdx.x;
    if (t < 16) {
        float n = 245760.f;
        float mean = g_sums[t] / n;
        float var = g_sums[16 + t] / n - mean * mean;
        g_stats[t] = mean;
        g_stats[16 + t] = rsqrtf(var + 1e-5f);
    }
}

// ---------------- K5: normalize + affine + relu (in place) ----------------------
__global__ void k_bn(float* __restrict__ out, const float* __restrict__ bn_g,
                     const float* __restrict__ bn_b) {
    int i4 = blockIdx.x * 256 + threadIdx.x;   // < 983040 float4s
    int ch = (i4 / 30720) & 15;
    float mean = g_stats[ch], inv = g_stats[16 + ch];
    float gg = bn_g[ch] * inv;
    float bb = bn_b[ch] - mean * gg;
    float4 v = ((float4*)out)[i4];
    v.x = fmaxf(v.x * gg + bb, 0.f);
    v.y = fmaxf(v.y * gg + bb, 0.f);
    v.z = fmaxf(v.z * gg + bb, 0.f);
    v.w = fmaxf(v.w * gg + bb, 0.f);
    ((float4*)out)[i4] = v;
}

// ---------------- launch --------------------------------------------------------
extern "C" void kernel_launch(void* const* d_in, const int* in_sizes, int n_in,
                              void* d_out, int out_size) {
    const float* x      = (const float*)d_in[0];
    const float* p_w    = (const float*)d_in[1];
    const float* p_b    = (const float*)d_in[2];
    const float* m_w    = (const float*)d_in[3];
    const float* m_b    = (const float*)d_in[4];
    const float* conv_w = (const float*)d_in[5];
    const float* comp_w = (const float*)d_in[6];
    const float* spec_w = (const float*)d_in[7];
    const float* bn_g   = (const float*)d_in[8];
    const float* bn_b   = (const float*)d_in[9];
    float* out = (float*)d_out;

    const int SM_K1 = CTS * CTS * XSTR * 4 + 9 * 32 * 28 * 4 + 128;   // 198848
    const int SM_K2 = DTS * DTS * XSTR * 4 + 9 * 32 * 32 * 4 + 128;   // 223616
    cudaFuncSetAttribute(k_conv1, cudaFuncAttributeMaxDynamicSharedMemorySize, SM_K1);
    cudaFuncSetAttribute(k_deform, cudaFuncAttributeMaxDynamicSharedMemorySize, SM_K2);

    k_prep<<<68, 256>>>(comp_w, conv_w, p_w, m_w);
    k_conv1<<<128, 512, SM_K1>>>(x, p_b, m_b);
    k_deform<<<128, 512, SM_K2>>>(x);
    k_spec<<<960, 256>>>(spec_w, out);
    k_stats<<<1, 32>>>();
    k_bn<<<3840, 256>>>(out, bn_g, bn_b);
    (void)in_sizes; (void)n_in; (void)out_size;
}